// round 1
// baseline (speedup 1.0000x reference)
#include <cuda_runtime.h>

#define BB 16
#define LATENT 128
#define NN 1024
#define EE 32768
#define HH 64
#define LL 4

// Scratch (device globals — no allocations allowed)
__device__ float d_g[BB * HH];
__device__ float d_h[BB * NN * HH];
__device__ float d_pos[BB * NN * 3];
__device__ float d_pacc[BB * NN * 3];
__device__ float d_agg[BB * NN * HH];
__device__ float d_cnt[NN];

__device__ __forceinline__ float silu(float x) {
    return x / (1.0f + __expf(-x));
}

// g = z @ Wg + bg   (16 x 64)
__global__ void g_kernel(const float* __restrict__ z,
                         const float* __restrict__ Wg,
                         const float* __restrict__ bg) {
    int t = blockIdx.x * blockDim.x + threadIdx.x;  // 0..1023
    int b = t >> 6, k = t & 63;
    float acc = bg[k];
    const float* zr = z + b * LATENT;
    #pragma unroll 8
    for (int i = 0; i < LATENT; i++) acc += zr[i] * Wg[i * HH + k];
    d_g[t] = acc;
}

// h[b,n,k] = nf[n] @ Wn + bn + g[b]
__global__ void h_kernel(const float* __restrict__ nf,
                         const float* __restrict__ Wn,
                         const float* __restrict__ bn) {
    int node = blockIdx.x;      // b*NN + n
    int k = threadIdx.x;
    int b = node >> 10, n = node & (NN - 1);
    float v = bn[k] + d_g[b * HH + k];
    v += nf[n * 3 + 0] * Wn[0 * HH + k]
       + nf[n * 3 + 1] * Wn[1 * HH + k]
       + nf[n * 3 + 2] * Wn[2 * HH + k];
    d_h[node * HH + k] = v;
}

__global__ void cnt_kernel(const int* __restrict__ row) {
    int e = blockIdx.x * blockDim.x + threadIdx.x;
    if (e < EE) atomicAdd(&d_cnt[row[e]], 1.0f);
}

// The big one: per (b, e) item, full edge MLP chain + scatter.
__global__ void __launch_bounds__(128) edge_kernel(
    const int* __restrict__ row, const int* __restrict__ col,
    const float* __restrict__ eW1, const float* __restrict__ eb1,
    const float* __restrict__ eW2, const float* __restrict__ eb2,
    const float* __restrict__ cW1, const float* __restrict__ cb1,
    const float* __restrict__ cW2) {
    extern __shared__ float s[];
    float* sW1 = s;                        // 129*64
    float* sW2 = sW1 + 129 * HH;           // 64*64
    float* sC1 = sW2 + HH * HH;            // 64*64
    float* sB1 = sC1 + HH * HH;            // 64
    float* sB2 = sB1 + HH;                 // 64
    float* sCB = sB2 + HH;                 // 64
    float* sCW = sCB + HH;                 // 64

    for (int i = threadIdx.x; i < 129 * HH; i += 128) sW1[i] = eW1[i];
    for (int i = threadIdx.x; i < HH * HH; i += 128) {
        sW2[i] = eW2[i];
        sC1[i] = cW1[i];
    }
    if (threadIdx.x < HH) {
        sB1[threadIdx.x] = eb1[threadIdx.x];
        sB2[threadIdx.x] = eb2[threadIdx.x];
        sCB[threadIdx.x] = cb1[threadIdx.x];
        sCW[threadIdx.x] = cW2[threadIdx.x];
    }
    __syncthreads();

    int item = blockIdx.x * 128 + threadIdx.x;  // exactly BB*EE items
    int b = item & (BB - 1);
    int e = item >> 4;
    int r = row[e], c = col[e];

    const float* hi = d_h + (size_t)(b * NN + r) * HH;
    const float* hj = d_h + (size_t)(b * NN + c) * HH;
    const float* pr = d_pos + (size_t)(b * NN + r) * 3;
    const float* pc = d_pos + (size_t)(b * NN + c) * 3;
    float dx = pr[0] - pc[0];
    float dy = pr[1] - pc[1];
    float dz = pr[2] - pc[2];
    float d2 = dx * dx + dy * dy + dz * dz;

    // ---- m1 = silu([hi, hj, d2] @ eW1 + eb1) ----
    float a[HH];
    #pragma unroll
    for (int k = 0; k < HH; k++) a[k] = sB1[k] + d2 * sW1[128 * HH + k];

    const float4* hi4 = reinterpret_cast<const float4*>(hi);
    #pragma unroll
    for (int i4 = 0; i4 < 16; i4++) {
        float4 v = hi4[i4];
        int base = (i4 * 4) * HH;
        #pragma unroll
        for (int k = 0; k < HH; k++) a[k] += v.x * sW1[base + k];
        #pragma unroll
        for (int k = 0; k < HH; k++) a[k] += v.y * sW1[base + HH + k];
        #pragma unroll
        for (int k = 0; k < HH; k++) a[k] += v.z * sW1[base + 2 * HH + k];
        #pragma unroll
        for (int k = 0; k < HH; k++) a[k] += v.w * sW1[base + 3 * HH + k];
    }
    const float4* hj4 = reinterpret_cast<const float4*>(hj);
    #pragma unroll
    for (int i4 = 0; i4 < 16; i4++) {
        float4 v = hj4[i4];
        int base = (64 + i4 * 4) * HH;
        #pragma unroll
        for (int k = 0; k < HH; k++) a[k] += v.x * sW1[base + k];
        #pragma unroll
        for (int k = 0; k < HH; k++) a[k] += v.y * sW1[base + HH + k];
        #pragma unroll
        for (int k = 0; k < HH; k++) a[k] += v.z * sW1[base + 2 * HH + k];
        #pragma unroll
        for (int k = 0; k < HH; k++) a[k] += v.w * sW1[base + 3 * HH + k];
    }
    #pragma unroll
    for (int k = 0; k < HH; k++) a[k] = silu(a[k]);

    // ---- m2 = silu(m1 @ eW2 + eb2) ----
    float m[HH];
    #pragma unroll
    for (int k = 0; k < HH; k++) m[k] = sB2[k];
    #pragma unroll
    for (int i = 0; i < HH; i++) {
        float v = a[i];
        #pragma unroll
        for (int k = 0; k < HH; k++) m[k] += v * sW2[i * HH + k];
    }
    #pragma unroll
    for (int k = 0; k < HH; k++) m[k] = silu(m[k]);

    // ---- w = silu(m2 @ cW1 + cb1) @ cW2 ----
    #pragma unroll
    for (int k = 0; k < HH; k++) a[k] = sCB[k];
    #pragma unroll
    for (int i = 0; i < HH; i++) {
        float v = m[i];
        #pragma unroll
        for (int k = 0; k < HH; k++) a[k] += v * sC1[i * HH + k];
    }
    float w = 0.0f;
    #pragma unroll
    for (int k = 0; k < HH; k++) w += silu(a[k]) * sCW[k];

    // ---- scatter ----
    float* aggp = d_agg + (size_t)(b * NN + r) * HH;
    #pragma unroll
    for (int k = 0; k < HH; k++) atomicAdd(&aggp[k], m[k]);

    float* pp = d_pacc + (size_t)(b * NN + r) * 3;
    atomicAdd(&pp[0], dx * w);
    atomicAdd(&pp[1], dy * w);
    atomicAdd(&pp[2], dz * w);
}

// Node update: u-MLP, residual, layernorm, pos update, clear accumulators.
__global__ void node_kernel(const float* __restrict__ nW1,
                            const float* __restrict__ nb1,
                            const float* __restrict__ nW2,
                            const float* __restrict__ nb2,
                            const float* __restrict__ lng,
                            const float* __restrict__ lnb) {
    int node = blockIdx.x;   // b*NN + n
    int k = threadIdx.x;     // 0..63
    __shared__ float x[2 * HH];
    __shared__ float y[HH];
    __shared__ float red[4];

    float hk = d_h[node * HH + k];
    float ak = d_agg[node * HH + k];
    x[k] = hk;
    x[HH + k] = ak;
    d_agg[node * HH + k] = 0.0f;   // clear for next layer
    __syncthreads();

    float u1 = nb1[k];
    #pragma unroll 8
    for (int i = 0; i < 2 * HH; i++) u1 += x[i] * nW1[i * HH + k];
    u1 = silu(u1);
    y[k] = u1;
    __syncthreads();

    float u = nb2[k];
    #pragma unroll 8
    for (int i = 0; i < HH; i++) u += y[i] * nW2[i * HH + k];
    float hn = hk + u;

    // layernorm over 64 features (2 warps)
    float v = hn;
    #pragma unroll
    for (int o = 16; o; o >>= 1) v += __shfl_xor_sync(0xffffffffu, v, o);
    if ((k & 31) == 0) red[k >> 5] = v;
    __syncthreads();
    float mu = (red[0] + red[1]) * (1.0f / HH);
    float dv = hn - mu;
    float v2 = dv * dv;
    #pragma unroll
    for (int o = 16; o; o >>= 1) v2 += __shfl_xor_sync(0xffffffffu, v2, o);
    if ((k & 31) == 0) red[2 + (k >> 5)] = v2;
    __syncthreads();
    float var = (red[2] + red[3]) * (1.0f / HH);
    d_h[node * HH + k] = dv * rsqrtf(var + 1e-5f) * lng[k] + lnb[k];

    if (k < 3) {
        int n = node & (NN - 1);
        float cntv = fmaxf(d_cnt[n], 1.0f);
        int pi = node * 3 + k;
        d_pos[pi] += d_pacc[pi] / cntv;
        d_pacc[pi] = 0.0f;   // clear for next layer
    }
}

__global__ void out_kernel(const float* __restrict__ oW1,
                           const float* __restrict__ ob1,
                           const float* __restrict__ oW2,
                           const float* __restrict__ ob2,
                           float* __restrict__ out) {
    int node = blockIdx.x;
    int k = threadIdx.x;
    __shared__ float x[HH];
    __shared__ float r[HH];
    x[k] = d_h[node * HH + k];
    __syncthreads();
    float acc = ob1[k];
    #pragma unroll 8
    for (int i = 0; i < HH; i++) acc += x[i] * oW1[i * HH + k];
    r[k] = fmaxf(acc, 0.0f);
    __syncthreads();
    if (k < 3) {
        float o = ob2[k];
        #pragma unroll 8
        for (int i = 0; i < HH; i++) o += r[i] * oW2[i * 3 + k];
        out[node * 3 + k] = o;
    }
}

extern "C" void kernel_launch(void* const* d_in, const int* in_sizes, int n_in,
                              void* d_out, int out_size) {
    const float* z   = (const float*)d_in[0];
    const int*   ei  = (const int*)d_in[1];
    const float* nf  = (const float*)d_in[2];
    const float* Wg  = (const float*)d_in[3];
    const float* bg  = (const float*)d_in[4];
    const float* Wn  = (const float*)d_in[5];
    const float* bn  = (const float*)d_in[6];
    const float* eW1 = (const float*)d_in[7];
    const float* eb1 = (const float*)d_in[8];
    const float* eW2 = (const float*)d_in[9];
    const float* eb2 = (const float*)d_in[10];
    const float* cW1 = (const float*)d_in[11];
    const float* cb1 = (const float*)d_in[12];
    const float* cW2 = (const float*)d_in[13];
    const float* nW1 = (const float*)d_in[14];
    const float* nb1 = (const float*)d_in[15];
    const float* nW2 = (const float*)d_in[16];
    const float* nb2 = (const float*)d_in[17];
    const float* lng = (const float*)d_in[18];
    const float* lnb = (const float*)d_in[19];
    const float* oW1 = (const float*)d_in[20];
    const float* ob1 = (const float*)d_in[21];
    const float* oW2 = (const float*)d_in[22];
    const float* ob2 = (const float*)d_in[23];

    void *pPos, *pPacc, *pAgg, *pCnt;
    cudaGetSymbolAddress(&pPos, d_pos);
    cudaGetSymbolAddress(&pPacc, d_pacc);
    cudaGetSymbolAddress(&pAgg, d_agg);
    cudaGetSymbolAddress(&pCnt, d_cnt);
    cudaMemsetAsync(pPos, 0, sizeof(float) * BB * NN * 3);
    cudaMemsetAsync(pPacc, 0, sizeof(float) * BB * NN * 3);
    cudaMemsetAsync(pAgg, 0, sizeof(float) * BB * NN * HH);
    cudaMemsetAsync(pCnt, 0, sizeof(float) * NN);

    const int SMEM = (129 * HH + 2 * HH * HH + 4 * HH) * (int)sizeof(float);
    cudaFuncSetAttribute((const void*)edge_kernel,
                         cudaFuncAttributeMaxDynamicSharedMemorySize, SMEM);

    g_kernel<<<1, 1024>>>(z, Wg, bg);
    h_kernel<<<BB * NN, HH>>>(nf, Wn, bn);
    cnt_kernel<<<EE / 256, 256>>>(ei);

    for (int l = 0; l < LL; l++) {
        edge_kernel<<<BB * EE / 128, 128, SMEM>>>(
            ei, ei + EE,
            eW1 + l * 129 * HH, eb1 + l * HH,
            eW2 + l * HH * HH, eb2 + l * HH,
            cW1 + l * HH * HH, cb1 + l * HH,
            cW2 + l * HH);
        node_kernel<<<BB * NN, HH>>>(
            nW1 + l * 2 * HH * HH, nb1 + l * HH,
            nW2 + l * HH * HH, nb2 + l * HH,
            lng + l * HH, lnb + l * HH);
    }

    out_kernel<<<BB * NN, HH>>>(oW1, ob1, oW2, ob2, (float*)d_out);
}

// round 2
// speedup vs baseline: 1.3745x; 1.3745x over previous
#include <cuda_runtime.h>

#define BB 16
#define LATENT 128
#define NN 1024
#define EE 32768
#define HH 64
#define LL 4

// ---- scratch (device globals; no allocations allowed) ----
__device__ float d_g[BB * HH];
__device__ float d_h[BB * NN * HH];
__device__ float d_pos[BB * NN * 3];
__device__ float d_p1[BB * NN * HH];
__device__ float d_p2[BB * NN * HH];
__device__ float d_m[(size_t)BB * EE * HH];   // per-(b,e) message, 128MB
__device__ float d_tr[(size_t)BB * EE * 4];   // per-(b,e) w*diff (padded to 4)
__device__ int   d_cnti[NN];
__device__ int   d_rowptr[NN + 1];
__device__ int   d_woff[NN];
__device__ int   d_eidx[EE];

__device__ __forceinline__ float silu(float x) {
    return x / (1.0f + __expf(-x));
}

// ---- g = z @ Wg + bg (16 x 64) ----
__global__ void g_kernel(const float* __restrict__ z,
                         const float* __restrict__ Wg,
                         const float* __restrict__ bg) {
    int t = blockIdx.x * blockDim.x + threadIdx.x;
    int b = t >> 6, k = t & 63;
    float acc = bg[k];
    const float* zr = z + b * LATENT;
    #pragma unroll 8
    for (int i = 0; i < LATENT; i++) acc += zr[i] * Wg[i * HH + k];
    d_g[t] = acc;
}

// ---- h[b,n,k] = nf[n] @ Wn + bn + g[b] ----
__global__ void h_kernel(const float* __restrict__ nf,
                         const float* __restrict__ Wn,
                         const float* __restrict__ bn) {
    int node = blockIdx.x;
    int k = threadIdx.x;
    int b = node >> 10, n = node & (NN - 1);
    float v = bn[k] + d_g[b * HH + k];
    v += nf[n * 3 + 0] * Wn[0 * HH + k]
       + nf[n * 3 + 1] * Wn[1 * HH + k]
       + nf[n * 3 + 2] * Wn[2 * HH + k];
    d_h[node * HH + k] = v;
}

// ---- CSR build ----
__global__ void hist_kernel(const int* __restrict__ row) {
    int e = blockIdx.x * blockDim.x + threadIdx.x;
    if (e < EE) atomicAdd(&d_cnti[row[e]], 1);
}

__global__ void scan_kernel() {
    __shared__ int sc[NN];
    int t = threadIdx.x;
    int v = d_cnti[t];
    sc[t] = v;
    __syncthreads();
    #pragma unroll
    for (int o = 1; o < NN; o <<= 1) {
        int u = (t >= o) ? sc[t - o] : 0;
        __syncthreads();
        sc[t] += u;
        __syncthreads();
    }
    d_rowptr[t + 1] = sc[t];
    if (t == 0) d_rowptr[0] = 0;
    d_woff[t] = sc[t] - v;
}

__global__ void scatter_kernel(const int* __restrict__ row) {
    int e = blockIdx.x * blockDim.x + threadIdx.x;
    if (e < EE) {
        int p = atomicAdd(&d_woff[row[e]], 1);
        d_eidx[p] = e;
    }
}

// ---- per-node projections through eW1: p1 = h @ eW1[0:64], p2 = h @ eW1[64:128] ----
__global__ void proj_kernel(const float* __restrict__ eW1) {
    int node = blockIdx.x;     // b*NN + n
    int k = threadIdx.x;       // 0..63
    __shared__ float x[HH];
    x[k] = d_h[node * HH + k];
    __syncthreads();
    float a1 = 0.0f, a2 = 0.0f;
    #pragma unroll 8
    for (int i = 0; i < HH; i++) {
        float v = x[i];
        a1 += v * eW1[i * HH + k];
        a2 += v * eW1[(HH + i) * HH + k];
    }
    d_p1[node * HH + k] = a1;
    d_p2[node * HH + k] = a2;
}

// ---- edge kernel: per (b,e) item; no atomics, streams m + trans to global ----
__global__ void __launch_bounds__(128) edge_kernel(
    const int* __restrict__ row, const int* __restrict__ col,
    const float* __restrict__ eW1row128,  // eW1 + 128*HH (the d2 row)
    const float* __restrict__ eb1,
    const float* __restrict__ eW2, const float* __restrict__ eb2,
    const float* __restrict__ cW1, const float* __restrict__ cb1,
    const float* __restrict__ cW2) {
    __shared__ float sW2[HH * HH];
    __shared__ float sC1[HH * HH];
    __shared__ float sB1[HH], sB2[HH], sCB[HH], sCW[HH], sWd[HH];

    for (int i = threadIdx.x; i < HH * HH; i += 128) {
        sW2[i] = eW2[i];
        sC1[i] = cW1[i];
    }
    if (threadIdx.x < HH) {
        sB1[threadIdx.x] = eb1[threadIdx.x];
        sB2[threadIdx.x] = eb2[threadIdx.x];
        sCB[threadIdx.x] = cb1[threadIdx.x];
        sCW[threadIdx.x] = cW2[threadIdx.x];
        sWd[threadIdx.x] = eW1row128[threadIdx.x];
    }
    __syncthreads();

    int item = blockIdx.x * 128 + threadIdx.x;   // exactly BB*EE items
    int b = item & (BB - 1);
    int e = item >> 4;
    int r = row[e], c = col[e];

    const float* pr = d_pos + (size_t)(b * NN + r) * 3;
    const float* pc = d_pos + (size_t)(b * NN + c) * 3;
    float dx = pr[0] - pc[0];
    float dy = pr[1] - pc[1];
    float dz = pr[2] - pc[2];
    float d2 = dx * dx + dy * dy + dz * dz;

    // a = silu(p1[b,r] + p2[b,c] + d2*W1row + b1)
    float a[HH];
    const float4* q1 = reinterpret_cast<const float4*>(d_p1 + (size_t)(b * NN + r) * HH);
    const float4* q2 = reinterpret_cast<const float4*>(d_p2 + (size_t)(b * NN + c) * HH);
    #pragma unroll
    for (int i4 = 0; i4 < 16; i4++) {
        float4 u = q1[i4];
        float4 v = q2[i4];
        int k0 = i4 * 4;
        a[k0 + 0] = u.x + v.x;
        a[k0 + 1] = u.y + v.y;
        a[k0 + 2] = u.z + v.z;
        a[k0 + 3] = u.w + v.w;
    }
    #pragma unroll
    for (int k = 0; k < HH; k++) a[k] = silu(a[k] + sB1[k] + d2 * sWd[k]);

    // m = silu(a @ eW2 + b2)
    float m[HH];
    #pragma unroll
    for (int k = 0; k < HH; k++) m[k] = sB2[k];
    #pragma unroll
    for (int i = 0; i < HH; i++) {
        float v = a[i];
        #pragma unroll
        for (int k = 0; k < HH; k++) m[k] += v * sW2[i * HH + k];
    }
    #pragma unroll
    for (int k = 0; k < HH; k++) m[k] = silu(m[k]);

    // w = silu(m @ cW1 + cb1) . cW2
    #pragma unroll
    for (int k = 0; k < HH; k++) a[k] = sCB[k];
    #pragma unroll
    for (int i = 0; i < HH; i++) {
        float v = m[i];
        #pragma unroll
        for (int k = 0; k < HH; k++) a[k] += v * sC1[i * HH + k];
    }
    float w = 0.0f;
    #pragma unroll
    for (int k = 0; k < HH; k++) w += silu(a[k]) * sCW[k];

    // stream out
    float4* om = reinterpret_cast<float4*>(d_m + (size_t)item * HH);
    #pragma unroll
    for (int i4 = 0; i4 < 16; i4++)
        om[i4] = make_float4(m[i4 * 4], m[i4 * 4 + 1], m[i4 * 4 + 2], m[i4 * 4 + 3]);

    float4* ot = reinterpret_cast<float4*>(d_tr + (size_t)item * 4);
    *ot = make_float4(dx * w, dy * w, dz * w, 0.0f);
}

// ---- gather + node update: CSR gather of m/trans, node MLP, LN, pos update ----
__global__ void node_kernel(const float* __restrict__ nW1,
                            const float* __restrict__ nb1,
                            const float* __restrict__ nW2,
                            const float* __restrict__ nb2,
                            const float* __restrict__ lng,
                            const float* __restrict__ lnb) {
    int node = blockIdx.x;   // b*NN + n
    int k = threadIdx.x;     // 0..63
    int b = node >> 10, n = node & (NN - 1);
    __shared__ float x[2 * HH];
    __shared__ float y[HH];
    __shared__ float red[4];

    int s = d_rowptr[n];
    int t = d_rowptr[n + 1];

    float agg = 0.0f;
    float tsum = 0.0f;
    for (int j = s; j < t; j++) {
        int e = d_eidx[j];
        size_t it = (size_t)e * BB + b;
        agg += d_m[it * HH + k];
        if (k < 3) tsum += d_tr[it * 4 + k];
    }

    float hk = d_h[node * HH + k];
    x[k] = hk;
    x[HH + k] = agg;
    __syncthreads();

    float u1 = nb1[k];
    #pragma unroll 8
    for (int i = 0; i < 2 * HH; i++) u1 += x[i] * nW1[i * HH + k];
    y[k] = silu(u1);
    __syncthreads();

    float u = nb2[k];
    #pragma unroll 8
    for (int i = 0; i < HH; i++) u += y[i] * nW2[i * HH + k];
    float hn = hk + u;

    // layernorm over 64 features
    float v = hn;
    #pragma unroll
    for (int o = 16; o; o >>= 1) v += __shfl_xor_sync(0xffffffffu, v, o);
    if ((k & 31) == 0) red[k >> 5] = v;
    __syncthreads();
    float mu = (red[0] + red[1]) * (1.0f / HH);
    float dv = hn - mu;
    float v2 = dv * dv;
    #pragma unroll
    for (int o = 16; o; o >>= 1) v2 += __shfl_xor_sync(0xffffffffu, v2, o);
    if ((k & 31) == 0) red[2 + (k >> 5)] = v2;
    __syncthreads();
    float var = (red[2] + red[3]) * (1.0f / HH);
    d_h[node * HH + k] = dv * rsqrtf(var + 1e-5f) * lng[k] + lnb[k];

    if (k < 3) {
        float cntv = fmaxf((float)(t - s), 1.0f);
        d_pos[node * 3 + k] += tsum / cntv;
    }
}

__global__ void out_kernel(const float* __restrict__ oW1,
                           const float* __restrict__ ob1,
                           const float* __restrict__ oW2,
                           const float* __restrict__ ob2,
                           float* __restrict__ out) {
    int node = blockIdx.x;
    int k = threadIdx.x;
    __shared__ float x[HH];
    __shared__ float r[HH];
    x[k] = d_h[node * HH + k];
    __syncthreads();
    float acc = ob1[k];
    #pragma unroll 8
    for (int i = 0; i < HH; i++) acc += x[i] * oW1[i * HH + k];
    r[k] = fmaxf(acc, 0.0f);
    __syncthreads();
    if (k < 3) {
        float o = ob2[k];
        #pragma unroll 8
        for (int i = 0; i < HH; i++) o += r[i] * oW2[i * 3 + k];
        out[node * 3 + k] = o;
    }
}

extern "C" void kernel_launch(void* const* d_in, const int* in_sizes, int n_in,
                              void* d_out, int out_size) {
    const float* z   = (const float*)d_in[0];
    const int*   ei  = (const int*)d_in[1];
    const float* nf  = (const float*)d_in[2];
    const float* Wg  = (const float*)d_in[3];
    const float* bg  = (const float*)d_in[4];
    const float* Wn  = (const float*)d_in[5];
    const float* bn  = (const float*)d_in[6];
    const float* eW1 = (const float*)d_in[7];
    const float* eb1 = (const float*)d_in[8];
    const float* eW2 = (const float*)d_in[9];
    const float* eb2 = (const float*)d_in[10];
    const float* cW1 = (const float*)d_in[11];
    const float* cb1 = (const float*)d_in[12];
    const float* cW2 = (const float*)d_in[13];
    const float* nW1 = (const float*)d_in[14];
    const float* nb1 = (const float*)d_in[15];
    const float* nW2 = (const float*)d_in[16];
    const float* nb2 = (const float*)d_in[17];
    const float* lng = (const float*)d_in[18];
    const float* lnb = (const float*)d_in[19];
    const float* oW1 = (const float*)d_in[20];
    const float* ob1 = (const float*)d_in[21];
    const float* oW2 = (const float*)d_in[22];
    const float* ob2 = (const float*)d_in[23];

    void *pPos, *pCnt;
    cudaGetSymbolAddress(&pPos, d_pos);
    cudaGetSymbolAddress(&pCnt, d_cnti);
    cudaMemsetAsync(pPos, 0, sizeof(float) * BB * NN * 3);
    cudaMemsetAsync(pCnt, 0, sizeof(int) * NN);

    g_kernel<<<1, 1024>>>(z, Wg, bg);
    h_kernel<<<BB * NN, HH>>>(nf, Wn, bn);
    hist_kernel<<<EE / 256, 256>>>(ei);
    scan_kernel<<<1, NN>>>();
    scatter_kernel<<<EE / 256, 256>>>(ei);

    for (int l = 0; l < LL; l++) {
        proj_kernel<<<BB * NN, HH>>>(eW1 + (size_t)l * 129 * HH);
        edge_kernel<<<BB * EE / 128, 128>>>(
            ei, ei + EE,
            eW1 + (size_t)l * 129 * HH + 128 * HH,
            eb1 + l * HH,
            eW2 + (size_t)l * HH * HH, eb2 + l * HH,
            cW1 + (size_t)l * HH * HH, cb1 + l * HH,
            cW2 + l * HH);
        node_kernel<<<BB * NN, HH>>>(
            nW1 + (size_t)l * 2 * HH * HH, nb1 + l * HH,
            nW2 + (size_t)l * HH * HH, nb2 + l * HH,
            lng + l * HH, lnb + l * HH);
    }

    out_kernel<<<BB * NN, HH>>>(oW1, ob1, oW2, ob2, (float*)d_out);
}

// round 4
// speedup vs baseline: 3.1700x; 2.3062x over previous
#include <cuda_runtime.h>
#include <cstdint>

#define BB 16
#define LATENT 128
#define NN 1024
#define EE 32768
#define HH 64
#define LL 4

// ---- scratch (device globals; no allocations allowed) ----
__device__ float d_g[BB * HH];
__device__ float d_h[BB * NN * HH];
__device__ float d_pos[BB * NN * 3];
__device__ float d_p1[BB * NN * HH];
__device__ float d_p2[BB * NN * HH];
__device__ float d_m[(size_t)BB * EE * HH];
__device__ float d_tr[(size_t)BB * EE * 4];
__device__ int   d_cnti[NN];
__device__ int   d_rowptr[NN + 1];
__device__ int   d_woff[NN];
__device__ int   d_eidx[EE];

__device__ __forceinline__ float silu(float x) {
    return x / (1.0f + __expf(-x));
}

__device__ __forceinline__ uint32_t f2tf32(float x) {
    uint32_t r;
    asm("cvt.rna.tf32.f32 %0, %1;" : "=r"(r) : "f"(x));
    return r;
}

__device__ __forceinline__ void mma_tf32(float* c, const uint32_t* a, const uint32_t* b) {
    asm volatile(
        "mma.sync.aligned.m16n8k8.row.col.f32.tf32.tf32.f32 "
        "{%0,%1,%2,%3}, {%4,%5,%6,%7}, {%8,%9}, {%0,%1,%2,%3};"
        : "+f"(c[0]), "+f"(c[1]), "+f"(c[2]), "+f"(c[3])
        : "r"(a[0]), "r"(a[1]), "r"(a[2]), "r"(a[3]), "r"(b[0]), "r"(b[1]));
}

// SMEM byte offsets
#define PAD_A 68          // A staging stride (floats): bank = 4*row+col -> conflict-free
#define PAD_B 72          // B stride (floats): bank = 8*k+n -> conflict-free
#define SME_A    0                           // 128*68*4 = 34816
#define SME_W2   34816                       // 64*72*4 = 18432
#define SME_C1   (SME_W2 + 18432)            // 18432
#define SME_BIAS (SME_C1 + 18432)            // 5*256 = 1280
#define SME_WV   (SME_BIAS + 1280)           // 512
#define SME_TOTAL (SME_WV + 512)

// ---- g = z @ Wg + bg ----
__global__ void g_kernel(const float* __restrict__ z,
                         const float* __restrict__ Wg,
                         const float* __restrict__ bg) {
    int t = blockIdx.x * blockDim.x + threadIdx.x;
    int b = t >> 6, k = t & 63;
    float acc = bg[k];
    const float* zr = z + b * LATENT;
    #pragma unroll 8
    for (int i = 0; i < LATENT; i++) acc += zr[i] * Wg[i * HH + k];
    d_g[t] = acc;
}

// ---- h[b,n,k] = nf[n] @ Wn + bn + g[b] ----
__global__ void h_kernel(const float* __restrict__ nf,
                         const float* __restrict__ Wn,
                         const float* __restrict__ bn) {
    int node = blockIdx.x;
    int k = threadIdx.x;
    int b = node >> 10, n = node & (NN - 1);
    float v = bn[k] + d_g[b * HH + k];
    v += nf[n * 3 + 0] * Wn[0 * HH + k]
       + nf[n * 3 + 1] * Wn[1 * HH + k]
       + nf[n * 3 + 2] * Wn[2 * HH + k];
    d_h[node * HH + k] = v;
}

// ---- CSR build ----
__global__ void hist_kernel(const int* __restrict__ row) {
    int e = blockIdx.x * blockDim.x + threadIdx.x;
    if (e < EE) atomicAdd(&d_cnti[row[e]], 1);
}

__global__ void scan_kernel() {
    __shared__ int sc[NN];
    int t = threadIdx.x;
    int v = d_cnti[t];
    sc[t] = v;
    __syncthreads();
    #pragma unroll
    for (int o = 1; o < NN; o <<= 1) {
        int u = (t >= o) ? sc[t - o] : 0;
        __syncthreads();
        sc[t] += u;
        __syncthreads();
    }
    d_rowptr[t + 1] = sc[t];
    if (t == 0) d_rowptr[0] = 0;
    d_woff[t] = sc[t] - v;
}

__global__ void scatter_kernel(const int* __restrict__ row) {
    int e = blockIdx.x * blockDim.x + threadIdx.x;
    if (e < EE) {
        int p = atomicAdd(&d_woff[row[e]], 1);
        d_eidx[p] = e;
    }
}

// ---- per-node projections ----
__global__ void proj_kernel(const float* __restrict__ eW1) {
    int node = blockIdx.x;
    int k = threadIdx.x;
    __shared__ float x[HH];
    x[k] = d_h[node * HH + k];
    __syncthreads();
    float a1 = 0.0f, a2 = 0.0f;
    #pragma unroll 8
    for (int i = 0; i < HH; i++) {
        float v = x[i];
        a1 += v * eW1[i * HH + k];
        a2 += v * eW1[(HH + i) * HH + k];
    }
    d_p1[node * HH + k] = a1;
    d_p2[node * HH + k] = a2;
}

// ---- fused edge kernel: scalar a-stage + 2x warp-level tf32 mma.sync GEMM ----
__global__ void __launch_bounds__(128) edge_kernel(
    const int* __restrict__ row, const int* __restrict__ col,
    const float* __restrict__ eW1row128, const float* __restrict__ eb1,
    const float* __restrict__ eW2, const float* __restrict__ eb2,
    const float* __restrict__ cW1, const float* __restrict__ cb1,
    const float* __restrict__ cW2) {
    extern __shared__ __align__(16) char smem[];
    float*    sAf = (float*)(smem + SME_A);
    uint32_t* sAu = (uint32_t*)(smem + SME_A);
    uint32_t* sW2 = (uint32_t*)(smem + SME_W2);
    uint32_t* sC1 = (uint32_t*)(smem + SME_C1);
    float*    sB1 = (float*)(smem + SME_BIAS);
    float*    sB2 = sB1 + 64;
    float*    sCB = sB1 + 128;
    float*    sCW = sB1 + 192;
    float*    sWD = sB1 + 256;
    float*    sWv = (float*)(smem + SME_WV);

    int tid = threadIdx.x;
    int wid = tid >> 5;
    int lane = tid & 31;
    int g = lane >> 2;        // group id (row within fragment)
    int tg = lane & 3;        // thread-in-group (col within fragment)

    // stage weights (tf32) and biases
    for (int idx = tid; idx < HH * HH; idx += 128) {
        int i = idx >> 6;     // k_in
        int n = idx & 63;     // n out
        sW2[i * PAD_B + n] = f2tf32(eW2[idx]);
        sC1[i * PAD_B + n] = f2tf32(cW1[idx]);
    }
    if (tid < HH) {
        sB1[tid] = eb1[tid];
        sB2[tid] = eb2[tid];
        sCB[tid] = cb1[tid];
        sCW[tid] = cW2[tid];
        sWD[tid] = eW1row128[tid];
    }
    __syncthreads();

    // ---- phase 1: scalar a-stage (exact fp32), store tf32 to staging ----
    int item = blockIdx.x * 128 + tid;
    int b = item & (BB - 1);
    int e = item >> 4;
    int r = row[e], c = col[e];

    const float* pr = d_pos + (size_t)(b * NN + r) * 3;
    const float* pc = d_pos + (size_t)(b * NN + c) * 3;
    float dx = pr[0] - pc[0];
    float dy = pr[1] - pc[1];
    float dz = pr[2] - pc[2];
    float d2 = dx * dx + dy * dy + dz * dz;

    const float4* q1 = reinterpret_cast<const float4*>(d_p1 + (size_t)(b * NN + r) * HH);
    const float4* q2 = reinterpret_cast<const float4*>(d_p2 + (size_t)(b * NN + c) * HH);
    uint4* arow4 = reinterpret_cast<uint4*>(sAu + tid * PAD_A);
    #pragma unroll
    for (int i4 = 0; i4 < 16; i4++) {
        float4 u = q1[i4];
        float4 v = q2[i4];
        int k0 = i4 * 4;
        float a0 = silu(u.x + v.x + sB1[k0 + 0] + d2 * sWD[k0 + 0]);
        float a1 = silu(u.y + v.y + sB1[k0 + 1] + d2 * sWD[k0 + 1]);
        float a2 = silu(u.z + v.z + sB1[k0 + 2] + d2 * sWD[k0 + 2]);
        float a3 = silu(u.w + v.w + sB1[k0 + 3] + d2 * sWD[k0 + 3]);
        uint4 t;
        t.x = f2tf32(a0); t.y = f2tf32(a1); t.z = f2tf32(a2); t.w = f2tf32(a3);
        arow4[i4] = t;
    }
    __syncwarp();

    int base = wid * 32;

    // ---- GEMM1: raw_m[128x64] = A @ eW2 ----
    float acc[2][8][4];
    #pragma unroll
    for (int mt = 0; mt < 2; mt++)
        #pragma unroll
        for (int j = 0; j < 8; j++)
            #pragma unroll
            for (int q = 0; q < 4; q++) acc[mt][j][q] = 0.0f;

    #pragma unroll
    for (int ks = 0; ks < 8; ks++) {
        uint32_t af[2][4];
        #pragma unroll
        for (int mt = 0; mt < 2; mt++) {
            int rr = base + mt * 16 + g;
            int cc = ks * 8 + tg;
            af[mt][0] = sAu[rr * PAD_A + cc];
            af[mt][1] = sAu[(rr + 8) * PAD_A + cc];
            af[mt][2] = sAu[rr * PAD_A + cc + 4];
            af[mt][3] = sAu[(rr + 8) * PAD_A + cc + 4];
        }
        uint32_t bf[8][2];
        #pragma unroll
        for (int j = 0; j < 8; j++) {
            bf[j][0] = sW2[(ks * 8 + tg) * PAD_B + j * 8 + g];
            bf[j][1] = sW2[(ks * 8 + tg + 4) * PAD_B + j * 8 + g];
        }
        #pragma unroll
        for (int mt = 0; mt < 2; mt++)
            #pragma unroll
            for (int j = 0; j < 8; j++) mma_tf32(acc[mt][j], af[mt], bf[j]);
    }

    // epilogue 1: m = silu(raw + b2), store float to own rows of staging
    #pragma unroll
    for (int mt = 0; mt < 2; mt++) {
        int r0 = base + mt * 16 + g;
        #pragma unroll
        for (int j = 0; j < 8; j++) {
            int c0 = j * 8 + tg * 2;
            sAf[r0 * PAD_A + c0]       = silu(acc[mt][j][0] + sB2[c0]);
            sAf[r0 * PAD_A + c0 + 1]   = silu(acc[mt][j][1] + sB2[c0 + 1]);
            sAf[(r0 + 8) * PAD_A + c0]     = silu(acc[mt][j][2] + sB2[c0]);
            sAf[(r0 + 8) * PAD_A + c0 + 1] = silu(acc[mt][j][3] + sB2[c0 + 1]);
        }
    }
    __syncwarp();

    // writeback m (float) + in-place tf32 convert for GEMM2
    {
        float4* myrow = reinterpret_cast<float4*>(sAf + tid * PAD_A);
        float4* om = reinterpret_cast<float4*>(d_m + (size_t)item * HH);
        #pragma unroll
        for (int i4 = 0; i4 < 16; i4++) {
            float4 v = myrow[i4];
            om[i4] = v;
            uint4 t;
            t.x = f2tf32(v.x); t.y = f2tf32(v.y);
            t.z = f2tf32(v.z); t.w = f2tf32(v.w);
            reinterpret_cast<uint4*>(myrow)[i4] = t;
        }
    }
    __syncwarp();

    // ---- GEMM2: raw_c[128x64] = M @ cW1 ----
    #pragma unroll
    for (int mt = 0; mt < 2; mt++)
        #pragma unroll
        for (int j = 0; j < 8; j++)
            #pragma unroll
            for (int q = 0; q < 4; q++) acc[mt][j][q] = 0.0f;

    #pragma unroll
    for (int ks = 0; ks < 8; ks++) {
        uint32_t af[2][4];
        #pragma unroll
        for (int mt = 0; mt < 2; mt++) {
            int rr = base + mt * 16 + g;
            int cc = ks * 8 + tg;
            af[mt][0] = sAu[rr * PAD_A + cc];
            af[mt][1] = sAu[(rr + 8) * PAD_A + cc];
            af[mt][2] = sAu[rr * PAD_A + cc + 4];
            af[mt][3] = sAu[(rr + 8) * PAD_A + cc + 4];
        }
        uint32_t bf[8][2];
        #pragma unroll
        for (int j = 0; j < 8; j++) {
            bf[j][0] = sC1[(ks * 8 + tg) * PAD_B + j * 8 + g];
            bf[j][1] = sC1[(ks * 8 + tg + 4) * PAD_B + j * 8 + g];
        }
        #pragma unroll
        for (int mt = 0; mt < 2; mt++)
            #pragma unroll
            for (int j = 0; j < 8; j++) mma_tf32(acc[mt][j], af[mt], bf[j]);
    }

    // epilogue 2: w = sum_n silu(raw + cb) * cw, quad-reduce
    float p[4] = {0.0f, 0.0f, 0.0f, 0.0f};
    #pragma unroll
    for (int mt = 0; mt < 2; mt++) {
        #pragma unroll
        for (int j = 0; j < 8; j++) {
            int c0 = j * 8 + tg * 2;
            int c1 = c0 + 1;
            p[mt * 2]     += silu(acc[mt][j][0] + sCB[c0]) * sCW[c0]
                           + silu(acc[mt][j][1] + sCB[c1]) * sCW[c1];
            p[mt * 2 + 1] += silu(acc[mt][j][2] + sCB[c0]) * sCW[c0]
                           + silu(acc[mt][j][3] + sCB[c1]) * sCW[c1];
        }
    }
    #pragma unroll
    for (int q = 0; q < 4; q++) {
        p[q] += __shfl_xor_sync(0xffffffffu, p[q], 1);
        p[q] += __shfl_xor_sync(0xffffffffu, p[q], 2);
    }
    if (tg == 0) {
        sWv[base + g]      = p[0];
        sWv[base + g + 8]  = p[1];
        sWv[base + 16 + g] = p[2];
        sWv[base + 24 + g] = p[3];
    }
    __syncwarp();

    float w = sWv[tid];
    float4* ot = reinterpret_cast<float4*>(d_tr + (size_t)item * 4);
    *ot = make_float4(dx * w, dy * w, dz * w, 0.0f);
}

// ---- gather + node update ----
__global__ void node_kernel(const float* __restrict__ nW1,
                            const float* __restrict__ nb1,
                            const float* __restrict__ nW2,
                            const float* __restrict__ nb2,
                            const float* __restrict__ lng,
                            const float* __restrict__ lnb) {
    int node = blockIdx.x;
    int k = threadIdx.x;
    int b = node >> 10, n = node & (NN - 1);
    __shared__ float x[2 * HH];
    __shared__ float y[HH];
    __shared__ float red[4];

    int s = d_rowptr[n];
    int t = d_rowptr[n + 1];

    float agg = 0.0f;
    float tsum = 0.0f;
    for (int j = s; j < t; j++) {
        int e = d_eidx[j];
        size_t it = (size_t)e * BB + b;
        agg += d_m[it * HH + k];
        if (k < 3) tsum += d_tr[it * 4 + k];
    }

    float hk = d_h[node * HH + k];
    x[k] = hk;
    x[HH + k] = agg;
    __syncthreads();

    float u1 = nb1[k];
    #pragma unroll 8
    for (int i = 0; i < 2 * HH; i++) u1 += x[i] * nW1[i * HH + k];
    y[k] = silu(u1);
    __syncthreads();

    float u = nb2[k];
    #pragma unroll 8
    for (int i = 0; i < HH; i++) u += y[i] * nW2[i * HH + k];
    float hn = hk + u;

    float v = hn;
    #pragma unroll
    for (int o = 16; o; o >>= 1) v += __shfl_xor_sync(0xffffffffu, v, o);
    if ((k & 31) == 0) red[k >> 5] = v;
    __syncthreads();
    float mu = (red[0] + red[1]) * (1.0f / HH);
    float dv = hn - mu;
    float v2 = dv * dv;
    #pragma unroll
    for (int o = 16; o; o >>= 1) v2 += __shfl_xor_sync(0xffffffffu, v2, o);
    if ((k & 31) == 0) red[2 + (k >> 5)] = v2;
    __syncthreads();
    float var = (red[2] + red[3]) * (1.0f / HH);
    d_h[node * HH + k] = dv * rsqrtf(var + 1e-5f) * lng[k] + lnb[k];

    if (k < 3) {
        float cntv = fmaxf((float)(t - s), 1.0f);
        d_pos[node * 3 + k] += tsum / cntv;
    }
}

__global__ void out_kernel(const float* __restrict__ oW1,
                           const float* __restrict__ ob1,
                           const float* __restrict__ oW2,
                           const float* __restrict__ ob2,
                           float* __restrict__ out) {
    int node = blockIdx.x;
    int k = threadIdx.x;
    __shared__ float x[HH];
    __shared__ float r[HH];
    x[k] = d_h[node * HH + k];
    __syncthreads();
    float acc = ob1[k];
    #pragma unroll 8
    for (int i = 0; i < HH; i++) acc += x[i] * oW1[i * HH + k];
    r[k] = fmaxf(acc, 0.0f);
    __syncthreads();
    if (k < 3) {
        float o = ob2[k];
        #pragma unroll 8
        for (int i = 0; i < HH; i++) o += r[i] * oW2[i * 3 + k];
        out[node * 3 + k] = o;
    }
}

extern "C" void kernel_launch(void* const* d_in, const int* in_sizes, int n_in,
                              void* d_out, int out_size) {
    const float* z   = (const float*)d_in[0];
    const int*   ei  = (const int*)d_in[1];
    const float* nf  = (const float*)d_in[2];
    const float* Wg  = (const float*)d_in[3];
    const float* bg  = (const float*)d_in[4];
    const float* Wn  = (const float*)d_in[5];
    const float* bn  = (const float*)d_in[6];
    const float* eW1 = (const float*)d_in[7];
    const float* eb1 = (const float*)d_in[8];
    const float* eW2 = (const float*)d_in[9];
    const float* eb2 = (const float*)d_in[10];
    const float* cW1 = (const float*)d_in[11];
    const float* cb1 = (const float*)d_in[12];
    const float* cW2 = (const float*)d_in[13];
    const float* nW1 = (const float*)d_in[14];
    const float* nb1 = (const float*)d_in[15];
    const float* nW2 = (const float*)d_in[16];
    const float* nb2 = (const float*)d_in[17];
    const float* lng = (const float*)d_in[18];
    const float* lnb = (const float*)d_in[19];
    const float* oW1 = (const float*)d_in[20];
    const float* ob1 = (const float*)d_in[21];
    const float* oW2 = (const float*)d_in[22];
    const float* ob2 = (const float*)d_in[23];

    void *pPos, *pCnt;
    cudaGetSymbolAddress(&pPos, d_pos);
    cudaGetSymbolAddress(&pCnt, d_cnti);
    cudaMemsetAsync(pPos, 0, sizeof(float) * BB * NN * 3);
    cudaMemsetAsync(pCnt, 0, sizeof(int) * NN);

    cudaFuncSetAttribute((const void*)edge_kernel,
                         cudaFuncAttributeMaxDynamicSharedMemorySize, SME_TOTAL);

    g_kernel<<<1, 1024>>>(z, Wg, bg);
    h_kernel<<<BB * NN, HH>>>(nf, Wn, bn);
    hist_kernel<<<EE / 256, 256>>>(ei);
    scan_kernel<<<1, NN>>>();
    scatter_kernel<<<EE / 256, 256>>>(ei);

    for (int l = 0; l < LL; l++) {
        proj_kernel<<<BB * NN, HH>>>(eW1 + (size_t)l * 129 * HH);
        edge_kernel<<<BB * EE / 128, 128, SME_TOTAL>>>(
            ei, ei + EE,
            eW1 + (size_t)l * 129 * HH + 128 * HH,
            eb1 + l * HH,
            eW2 + (size_t)l * HH * HH, eb2 + l * HH,
            cW1 + (size_t)l * HH * HH, cb1 + l * HH,
            cW2 + l * HH);
        node_kernel<<<BB * NN, HH>>>(
            nW1 + (size_t)l * 2 * HH * HH, nb1 + l * HH,
            nW2 + (size_t)l * HH * HH, nb2 + l * HH,
            lng + l * HH, lnb + l * HH);
    }

    out_kernel<<<BB * NN, HH>>>(oW1, ob1, oW2, ob2, (float*)d_out);
}

// round 5
// speedup vs baseline: 3.1867x; 1.0053x over previous
#include <cuda_runtime.h>
#include <cstdint>

#define BB 16
#define LATENT 128
#define NN 1024
#define EE 32768
#define HH 64
#define LL 4
#define NTILES (BB * EE / 128)   // 4096 tiles of 128 items
#define EDGE_GRID 444            // 148 SMs * 3 CTAs

// ---- scratch (device globals; no allocations allowed) ----
__device__ float d_g[BB * HH];
__device__ float d_h[BB * NN * HH];
__device__ float d_pos[BB * NN * 3];
__device__ float d_p1[BB * NN * HH];
__device__ float d_p2[BB * NN * HH];
__device__ float d_m[(size_t)BB * EE * HH];
__device__ float d_tr[(size_t)BB * EE * 4];
__device__ int   d_cnti[NN];
__device__ int   d_rowptr[NN + 1];
__device__ int   d_woff[NN];
__device__ int   d_eidx[EE];

__device__ __forceinline__ float silu(float x) {
    return x / (1.0f + __expf(-x));
}

__device__ __forceinline__ uint32_t f2tf32(float x) {
    uint32_t r;
    asm("cvt.rna.tf32.f32 %0, %1;" : "=r"(r) : "f"(x));
    return r;
}

__device__ __forceinline__ void mma_tf32(float* c, const uint32_t* a, const uint32_t* b) {
    asm volatile(
        "mma.sync.aligned.m16n8k8.row.col.f32.tf32.tf32.f32 "
        "{%0,%1,%2,%3}, {%4,%5,%6,%7}, {%8,%9}, {%0,%1,%2,%3};"
        : "+f"(c[0]), "+f"(c[1]), "+f"(c[2]), "+f"(c[3])
        : "r"(a[0]), "r"(a[1]), "r"(a[2]), "r"(a[3]), "r"(b[0]), "r"(b[1]));
}

// SMEM layout
#define PAD_A 68
#define PAD_B 72
#define SME_A    0                           // 128*68*4 = 34816
#define SME_W2   34816                       // 64*72*4 = 18432
#define SME_C1   (SME_W2 + 18432)
#define SME_BIAS (SME_C1 + 18432)            // 5*256
#define SME_WV   (SME_BIAS + 1280)
#define SME_TOTAL (SME_WV + 512)

// ---- g = z @ Wg + bg ----
__global__ void g_kernel(const float* __restrict__ z,
                         const float* __restrict__ Wg,
                         const float* __restrict__ bg) {
    int t = blockIdx.x * blockDim.x + threadIdx.x;
    int b = t >> 6, k = t & 63;
    float acc = bg[k];
    const float* zr = z + b * LATENT;
    #pragma unroll 8
    for (int i = 0; i < LATENT; i++) acc += zr[i] * Wg[i * HH + k];
    d_g[t] = acc;
}

// ---- h[b,n,k] = nf[n] @ Wn + bn + g[b] ----
__global__ void h_kernel(const float* __restrict__ nf,
                         const float* __restrict__ Wn,
                         const float* __restrict__ bn) {
    int node = blockIdx.x;
    int k = threadIdx.x;
    int b = node >> 10, n = node & (NN - 1);
    float v = bn[k] + d_g[b * HH + k];
    v += nf[n * 3 + 0] * Wn[0 * HH + k]
       + nf[n * 3 + 1] * Wn[1 * HH + k]
       + nf[n * 3 + 2] * Wn[2 * HH + k];
    d_h[node * HH + k] = v;
}

// ---- CSR build ----
__global__ void hist_kernel(const int* __restrict__ row) {
    int e = blockIdx.x * blockDim.x + threadIdx.x;
    if (e < EE) atomicAdd(&d_cnti[row[e]], 1);
}

__global__ void scan_kernel() {
    __shared__ int sc[NN];
    int t = threadIdx.x;
    int v = d_cnti[t];
    sc[t] = v;
    __syncthreads();
    #pragma unroll
    for (int o = 1; o < NN; o <<= 1) {
        int u = (t >= o) ? sc[t - o] : 0;
        __syncthreads();
        sc[t] += u;
        __syncthreads();
    }
    d_rowptr[t + 1] = sc[t];
    if (t == 0) d_rowptr[0] = 0;
    d_woff[t] = sc[t] - v;
}

__global__ void scatter_kernel(const int* __restrict__ row) {
    int e = blockIdx.x * blockDim.x + threadIdx.x;
    if (e < EE) {
        int p = atomicAdd(&d_woff[row[e]], 1);
        d_eidx[p] = e;
    }
}

// ---- per-node projections ----
__global__ void proj_kernel(const float* __restrict__ eW1) {
    int node = blockIdx.x;
    int k = threadIdx.x;
    __shared__ float x[HH];
    x[k] = d_h[node * HH + k];
    __syncthreads();
    float a1 = 0.0f, a2 = 0.0f;
    #pragma unroll 8
    for (int i = 0; i < HH; i++) {
        float v = x[i];
        a1 += v * eW1[i * HH + k];
        a2 += v * eW1[(HH + i) * HH + k];
    }
    d_p1[node * HH + k] = a1;
    d_p2[node * HH + k] = a2;
}

// ---- fused edge kernel: persistent tile loop; 2x warp-level tf32 mma.sync ----
__global__ void __launch_bounds__(128) edge_kernel(
    const int* __restrict__ row, const int* __restrict__ col,
    const float* __restrict__ eW1row128, const float* __restrict__ eb1,
    const float* __restrict__ eW2, const float* __restrict__ eb2,
    const float* __restrict__ cW1, const float* __restrict__ cb1,
    const float* __restrict__ cW2) {
    extern __shared__ __align__(16) char smem[];
    float*    sAf = (float*)(smem + SME_A);
    uint32_t* sAu = (uint32_t*)(smem + SME_A);
    uint32_t* sW2 = (uint32_t*)(smem + SME_W2);
    uint32_t* sC1 = (uint32_t*)(smem + SME_C1);
    float*    sB1 = (float*)(smem + SME_BIAS);
    float*    sB2 = sB1 + 64;
    float*    sCB = sB1 + 128;
    float*    sCW = sB1 + 192;
    float*    sWD = sB1 + 256;
    float*    sWv = (float*)(smem + SME_WV);

    int tid = threadIdx.x;
    int wid = tid >> 5;
    int lane = tid & 31;
    int g = lane >> 2;
    int tg = lane & 3;
    int base = wid * 32;

    // one-time weight/bias staging
    for (int idx = tid; idx < HH * HH; idx += 128) {
        int i = idx >> 6;
        int n = idx & 63;
        sW2[i * PAD_B + n] = f2tf32(eW2[idx]);
        sC1[i * PAD_B + n] = f2tf32(cW1[idx]);
    }
    if (tid < HH) {
        sB1[tid] = eb1[tid];
        sB2[tid] = eb2[tid];
        sCB[tid] = cb1[tid];
        sCW[tid] = cW2[tid];
        sWD[tid] = eW1row128[tid];
    }
    __syncthreads();

    for (int tile = blockIdx.x; tile < NTILES; tile += EDGE_GRID) {
        int item = tile * 128 + tid;
        int b = item & (BB - 1);
        int e = item >> 4;
        int r = row[e], c = col[e];

        const float* pr = d_pos + (size_t)(b * NN + r) * 3;
        const float* pc = d_pos + (size_t)(b * NN + c) * 3;
        float dx = pr[0] - pc[0];
        float dy = pr[1] - pc[1];
        float dz = pr[2] - pc[2];
        float d2 = dx * dx + dy * dy + dz * dz;

        const float4* q1 = reinterpret_cast<const float4*>(d_p1 + (size_t)(b * NN + r) * HH);
        const float4* q2 = reinterpret_cast<const float4*>(d_p2 + (size_t)(b * NN + c) * HH);
        uint4* arow4 = reinterpret_cast<uint4*>(sAu + tid * PAD_A);
        #pragma unroll
        for (int i4 = 0; i4 < 16; i4++) {
            float4 u = q1[i4];
            float4 v = q2[i4];
            int k0 = i4 * 4;
            float a0 = silu(u.x + v.x + sB1[k0 + 0] + d2 * sWD[k0 + 0]);
            float a1 = silu(u.y + v.y + sB1[k0 + 1] + d2 * sWD[k0 + 1]);
            float a2 = silu(u.z + v.z + sB1[k0 + 2] + d2 * sWD[k0 + 2]);
            float a3 = silu(u.w + v.w + sB1[k0 + 3] + d2 * sWD[k0 + 3]);
            uint4 t;
            t.x = f2tf32(a0); t.y = f2tf32(a1); t.z = f2tf32(a2); t.w = f2tf32(a3);
            arow4[i4] = t;
        }
        __syncwarp();

        // ---- GEMM1: raw_m = A @ eW2 ----
        float acc[2][8][4];
        #pragma unroll
        for (int mt = 0; mt < 2; mt++)
            #pragma unroll
            for (int j = 0; j < 8; j++)
                #pragma unroll
                for (int q = 0; q < 4; q++) acc[mt][j][q] = 0.0f;

        #pragma unroll
        for (int ks = 0; ks < 8; ks++) {
            uint32_t af[2][4];
            #pragma unroll
            for (int mt = 0; mt < 2; mt++) {
                int rr = base + mt * 16 + g;
                int cc = ks * 8 + tg;
                af[mt][0] = sAu[rr * PAD_A + cc];
                af[mt][1] = sAu[(rr + 8) * PAD_A + cc];
                af[mt][2] = sAu[rr * PAD_A + cc + 4];
                af[mt][3] = sAu[(rr + 8) * PAD_A + cc + 4];
            }
            uint32_t bf[8][2];
            #pragma unroll
            for (int j = 0; j < 8; j++) {
                bf[j][0] = sW2[(ks * 8 + tg) * PAD_B + j * 8 + g];
                bf[j][1] = sW2[(ks * 8 + tg + 4) * PAD_B + j * 8 + g];
            }
            #pragma unroll
            for (int mt = 0; mt < 2; mt++)
                #pragma unroll
                for (int j = 0; j < 8; j++) mma_tf32(acc[mt][j], af[mt], bf[j]);
        }

        // epilogue 1: m = silu(raw + b2)
        #pragma unroll
        for (int mt = 0; mt < 2; mt++) {
            int r0 = base + mt * 16 + g;
            #pragma unroll
            for (int j = 0; j < 8; j++) {
                int c0 = j * 8 + tg * 2;
                sAf[r0 * PAD_A + c0]           = silu(acc[mt][j][0] + sB2[c0]);
                sAf[r0 * PAD_A + c0 + 1]       = silu(acc[mt][j][1] + sB2[c0 + 1]);
                sAf[(r0 + 8) * PAD_A + c0]     = silu(acc[mt][j][2] + sB2[c0]);
                sAf[(r0 + 8) * PAD_A + c0 + 1] = silu(acc[mt][j][3] + sB2[c0 + 1]);
            }
        }
        __syncwarp();

        // writeback m + in-place tf32 convert
        {
            float4* myrow = reinterpret_cast<float4*>(sAf + tid * PAD_A);
            float4* om = reinterpret_cast<float4*>(d_m + (size_t)item * HH);
            #pragma unroll
            for (int i4 = 0; i4 < 16; i4++) {
                float4 v = myrow[i4];
                om[i4] = v;
                uint4 t;
                t.x = f2tf32(v.x); t.y = f2tf32(v.y);
                t.z = f2tf32(v.z); t.w = f2tf32(v.w);
                reinterpret_cast<uint4*>(myrow)[i4] = t;
            }
        }
        __syncwarp();

        // ---- GEMM2: raw_c = M @ cW1 ----
        #pragma unroll
        for (int mt = 0; mt < 2; mt++)
            #pragma unroll
            for (int j = 0; j < 8; j++)
                #pragma unroll
                for (int q = 0; q < 4; q++) acc[mt][j][q] = 0.0f;

        #pragma unroll
        for (int ks = 0; ks < 8; ks++) {
            uint32_t af[2][4];
            #pragma unroll
            for (int mt = 0; mt < 2; mt++) {
                int rr = base + mt * 16 + g;
                int cc = ks * 8 + tg;
                af[mt][0] = sAu[rr * PAD_A + cc];
                af[mt][1] = sAu[(rr + 8) * PAD_A + cc];
                af[mt][2] = sAu[rr * PAD_A + cc + 4];
                af[mt][3] = sAu[(rr + 8) * PAD_A + cc + 4];
            }
            uint32_t bf[8][2];
            #pragma unroll
            for (int j = 0; j < 8; j++) {
                bf[j][0] = sC1[(ks * 8 + tg) * PAD_B + j * 8 + g];
                bf[j][1] = sC1[(ks * 8 + tg + 4) * PAD_B + j * 8 + g];
            }
            #pragma unroll
            for (int mt = 0; mt < 2; mt++)
                #pragma unroll
                for (int j = 0; j < 8; j++) mma_tf32(acc[mt][j], af[mt], bf[j]);
        }

        // epilogue 2: w = sum_n silu(raw + cb) * cw
        float p[4] = {0.0f, 0.0f, 0.0f, 0.0f};
        #pragma unroll
        for (int mt = 0; mt < 2; mt++) {
            #pragma unroll
            for (int j = 0; j < 8; j++) {
                int c0 = j * 8 + tg * 2;
                int c1 = c0 + 1;
                p[mt * 2]     += silu(acc[mt][j][0] + sCB[c0]) * sCW[c0]
                               + silu(acc[mt][j][1] + sCB[c1]) * sCW[c1];
                p[mt * 2 + 1] += silu(acc[mt][j][2] + sCB[c0]) * sCW[c0]
                               + silu(acc[mt][j][3] + sCB[c1]) * sCW[c1];
            }
        }
        #pragma unroll
        for (int q = 0; q < 4; q++) {
            p[q] += __shfl_xor_sync(0xffffffffu, p[q], 1);
            p[q] += __shfl_xor_sync(0xffffffffu, p[q], 2);
        }
        if (tg == 0) {
            sWv[base + g]      = p[0];
            sWv[base + g + 8]  = p[1];
            sWv[base + 16 + g] = p[2];
            sWv[base + 24 + g] = p[3];
        }
        __syncwarp();

        float w = sWv[tid];
        float4* ot = reinterpret_cast<float4*>(d_tr + (size_t)item * 4);
        *ot = make_float4(dx * w, dy * w, dz * w, 0.0f);
        __syncwarp();
    }
}

// ---- gather + node update ----
__global__ void node_kernel(const float* __restrict__ nW1,
                            const float* __restrict__ nb1,
                            const float* __restrict__ nW2,
                            const float* __restrict__ nb2,
                            const float* __restrict__ lng,
                            const float* __restrict__ lnb) {
    int node = blockIdx.x;
    int k = threadIdx.x;
    int b = node >> 10, n = node & (NN - 1);
    __shared__ float x[2 * HH];
    __shared__ float y[HH];
    __shared__ float red[4];

    int s = d_rowptr[n];
    int t = d_rowptr[n + 1];

    float agg = 0.0f;
    float tsum = 0.0f;
    for (int j = s; j < t; j++) {
        int e = d_eidx[j];
        size_t it = (size_t)e * BB + b;
        agg += d_m[it * HH + k];
        if (k < 3) tsum += d_tr[it * 4 + k];
    }

    float hk = d_h[node * HH + k];
    x[k] = hk;
    x[HH + k] = agg;
    __syncthreads();

    float u1 = nb1[k];
    #pragma unroll 8
    for (int i = 0; i < 2 * HH; i++) u1 += x[i] * nW1[i * HH + k];
    y[k] = silu(u1);
    __syncthreads();

    float u = nb2[k];
    #pragma unroll 8
    for (int i = 0; i < HH; i++) u += y[i] * nW2[i * HH + k];
    float hn = hk + u;

    float v = hn;
    #pragma unroll
    for (int o = 16; o; o >>= 1) v += __shfl_xor_sync(0xffffffffu, v, o);
    if ((k & 31) == 0) red[k >> 5] = v;
    __syncthreads();
    float mu = (red[0] + red[1]) * (1.0f / HH);
    float dv = hn - mu;
    float v2 = dv * dv;
    #pragma unroll
    for (int o = 16; o; o >>= 1) v2 += __shfl_xor_sync(0xffffffffu, v2, o);
    if ((k & 31) == 0) red[2 + (k >> 5)] = v2;
    __syncthreads();
    float var = (red[2] + red[3]) * (1.0f / HH);
    d_h[node * HH + k] = dv * rsqrtf(var + 1e-5f) * lng[k] + lnb[k];

    if (k < 3) {
        float cntv = fmaxf((float)(t - s), 1.0f);
        d_pos[node * 3 + k] += tsum / cntv;
    }
}

__global__ void out_kernel(const float* __restrict__ oW1,
                           const float* __restrict__ ob1,
                           const float* __restrict__ oW2,
                           const float* __restrict__ ob2,
                           float* __restrict__ out) {
    int node = blockIdx.x;
    int k = threadIdx.x;
    __shared__ float x[HH];
    __shared__ float r[HH];
    x[k] = d_h[node * HH + k];
    __syncthreads();
    float acc = ob1[k];
    #pragma unroll 8
    for (int i = 0; i < HH; i++) acc += x[i] * oW1[i * HH + k];
    r[k] = fmaxf(acc, 0.0f);
    __syncthreads();
    if (k < 3) {
        float o = ob2[k];
        #pragma unroll 8
        for (int i = 0; i < HH; i++) o += r[i] * oW2[i * 3 + k];
        out[node * 3 + k] = o;
    }
}

extern "C" void kernel_launch(void* const* d_in, const int* in_sizes, int n_in,
                              void* d_out, int out_size) {
    const float* z   = (const float*)d_in[0];
    const int*   ei  = (const int*)d_in[1];
    const float* nf  = (const float*)d_in[2];
    const float* Wg  = (const float*)d_in[3];
    const float* bg  = (const float*)d_in[4];
    const float* Wn  = (const float*)d_in[5];
    const float* bn  = (const float*)d_in[6];
    const float* eW1 = (const float*)d_in[7];
    const float* eb1 = (const float*)d_in[8];
    const float* eW2 = (const float*)d_in[9];
    const float* eb2 = (const float*)d_in[10];
    const float* cW1 = (const float*)d_in[11];
    const float* cb1 = (const float*)d_in[12];
    const float* cW2 = (const float*)d_in[13];
    const float* nW1 = (const float*)d_in[14];
    const float* nb1 = (const float*)d_in[15];
    const float* nW2 = (const float*)d_in[16];
    const float* nb2 = (const float*)d_in[17];
    const float* lng = (const float*)d_in[18];
    const float* lnb = (const float*)d_in[19];
    const float* oW1 = (const float*)d_in[20];
    const float* ob1 = (const float*)d_in[21];
    const float* oW2 = (const float*)d_in[22];
    const float* ob2 = (const float*)d_in[23];

    void *pPos, *pCnt;
    cudaGetSymbolAddress(&pPos, d_pos);
    cudaGetSymbolAddress(&pCnt, d_cnti);
    cudaMemsetAsync(pPos, 0, sizeof(float) * BB * NN * 3);
    cudaMemsetAsync(pCnt, 0, sizeof(int) * NN);

    cudaFuncSetAttribute((const void*)edge_kernel,
                         cudaFuncAttributeMaxDynamicSharedMemorySize, SME_TOTAL);

    g_kernel<<<1, 1024>>>(z, Wg, bg);
    h_kernel<<<BB * NN, HH>>>(nf, Wn, bn);
    hist_kernel<<<EE / 256, 256>>>(ei);
    scan_kernel<<<1, NN>>>();
    scatter_kernel<<<EE / 256, 256>>>(ei);

    for (int l = 0; l < LL; l++) {
        proj_kernel<<<BB * NN, HH>>>(eW1 + (size_t)l * 129 * HH);
        edge_kernel<<<EDGE_GRID, 128, SME_TOTAL>>>(
            ei, ei + EE,
            eW1 + (size_t)l * 129 * HH + 128 * HH,
            eb1 + l * HH,
            eW2 + (size_t)l * HH * HH, eb2 + l * HH,
            cW1 + (size_t)l * HH * HH, cb1 + l * HH,
            cW2 + l * HH);
        node_kernel<<<BB * NN, HH>>>(
            nW1 + (size_t)l * 2 * HH * HH, nb1 + l * HH,
            nW2 + (size_t)l * HH * HH, nb2 + l * HH,
            lng + l * HH, lnb + l * HH);
    }

    out_kernel<<<BB * NN, HH>>>(oW1, ob1, oW2, ob2, (float*)d_out);
}

// round 6
// speedup vs baseline: 4.3139x; 1.3537x over previous
#include <cuda_runtime.h>
#include <cstdint>

#define BB 16
#define LATENT 128
#define NN 1024
#define EE 32768
#define HH 64
#define LL 4
#define NTILES (BB * EE / 128)
#define EDGE_GRID 592            // 148 SMs * 4 CTAs

// ---- scratch (device globals; no allocations allowed) ----
__device__ float d_g[BB * HH];
__device__ float d_h[BB * NN * HH];
__device__ float d_p1[BB * NN * HH];
__device__ float d_p2[BB * NN * HH];
__device__ float d_m[(size_t)BB * EE * HH];
__device__ int   d_rowptr[NN + 1];
__device__ int   d_eidx[EE];

__device__ __forceinline__ float silu(float x) {
    return x / (1.0f + __expf(-x));
}

__device__ __forceinline__ uint32_t f2tf32(float x) {
    uint32_t r;
    asm("cvt.rna.tf32.f32 %0, %1;" : "=r"(r) : "f"(x));
    return r;
}

__device__ __forceinline__ void mma_tf32(float* c, const uint32_t* a, const uint32_t* b) {
    asm volatile(
        "mma.sync.aligned.m16n8k8.row.col.f32.tf32.tf32.f32 "
        "{%0,%1,%2,%3}, {%4,%5,%6,%7}, {%8,%9}, {%0,%1,%2,%3};"
        : "+f"(c[0]), "+f"(c[1]), "+f"(c[2]), "+f"(c[3])
        : "r"(a[0]), "r"(a[1]), "r"(a[2]), "r"(a[3]), "r"(b[0]), "r"(b[1]));
}

// SMEM layout (edge kernel)
#define PAD_A 68
#define PAD_B 72
#define SME_A    0                           // 128*68*4 = 34816
#define SME_W2   34816                       // 64*72*4 = 18432
#define SME_BIAS (SME_W2 + 18432)            // b2: 256
#define SME_TOTAL (SME_BIAS + 256)

// ---- g = z @ Wg + bg ----
__global__ void g_kernel(const float* __restrict__ z,
                         const float* __restrict__ Wg,
                         const float* __restrict__ bg) {
    int t = blockIdx.x * blockDim.x + threadIdx.x;
    int b = t >> 6, k = t & 63;
    float acc = bg[k];
    const float* zr = z + b * LATENT;
    #pragma unroll 8
    for (int i = 0; i < LATENT; i++) acc += zr[i] * Wg[i * HH + k];
    d_g[t] = acc;
}

// ---- h[b,n,k] = nf[n] @ Wn + bn + g[b] ----
__global__ void h_kernel(const float* __restrict__ nf,
                         const float* __restrict__ Wn,
                         const float* __restrict__ bn) {
    int node = blockIdx.x;
    int k = threadIdx.x;
    int b = node >> 10, n = node & (NN - 1);
    float v = bn[k] + d_g[b * HH + k];
    v += nf[n * 3 + 0] * Wn[0 * HH + k]
       + nf[n * 3 + 1] * Wn[1 * HH + k]
       + nf[n * 3 + 2] * Wn[2 * HH + k];
    d_h[node * HH + k] = v;
}

// ---- CSR build in one single-block kernel: hist + scan + scatter ----
__global__ void csr_kernel(const int* __restrict__ row) {
    __shared__ int sc[NN];
    __shared__ int wo[NN];
    int t = threadIdx.x;   // 0..1023
    sc[t] = 0;
    __syncthreads();
    for (int e = t; e < EE; e += 1024) atomicAdd(&sc[row[e]], 1);
    __syncthreads();
    int v = sc[t];
    #pragma unroll
    for (int o = 1; o < NN; o <<= 1) {
        int u = (t >= o) ? sc[t - o] : 0;
        __syncthreads();
        sc[t] += u;
        __syncthreads();
    }
    d_rowptr[t + 1] = sc[t];
    if (t == 0) d_rowptr[0] = 0;
    wo[t] = sc[t] - v;
    __syncthreads();
    for (int e = t; e < EE; e += 1024) {
        int p = atomicAdd(&wo[row[e]], 1);
        d_eidx[p] = e;
    }
}

// ---- p1 = h @ eW1[0:64] + eb1 ----
__global__ void proj1_kernel(const float* __restrict__ eW1,
                             const float* __restrict__ eb1) {
    int node = blockIdx.x;
    int k = threadIdx.x;
    __shared__ float x[HH];
    x[k] = d_h[node * HH + k];
    __syncthreads();
    float a1 = eb1[k];
    #pragma unroll 8
    for (int i = 0; i < HH; i++) a1 += x[i] * eW1[i * HH + k];
    d_p1[node * HH + k] = a1;
}

// ---- p2 = h @ eW1[64:128] ----
__global__ void proj2_kernel(const float* __restrict__ eW1) {
    int node = blockIdx.x;
    int k = threadIdx.x;
    __shared__ float x[HH];
    x[k] = d_h[node * HH + k];
    __syncthreads();
    float a2 = 0.0f;
    #pragma unroll 8
    for (int i = 0; i < HH; i++) a2 += x[i] * eW1[(HH + i) * HH + k];
    d_p2[node * HH + k] = a2;
}

// ---- fused edge kernel: persistent; a-stage + single tf32 mma.sync GEMM ----
__global__ void __launch_bounds__(128) edge_kernel(
    const int* __restrict__ row, const int* __restrict__ col,
    const float* __restrict__ eW2, const float* __restrict__ eb2) {
    extern __shared__ __align__(16) char smem[];
    float*    sAf = (float*)(smem + SME_A);
    uint32_t* sAu = (uint32_t*)(smem + SME_A);
    uint32_t* sW2 = (uint32_t*)(smem + SME_W2);
    float*    sB2 = (float*)(smem + SME_BIAS);

    int tid = threadIdx.x;
    int wid = tid >> 5;
    int lane = tid & 31;
    int g = lane >> 2;
    int tg = lane & 3;
    int base = wid * 32;

    for (int idx = tid; idx < HH * HH; idx += 128) {
        int i = idx >> 6;
        int n = idx & 63;
        sW2[i * PAD_B + n] = f2tf32(eW2[idx]);
    }
    if (tid < HH) sB2[tid] = eb2[tid];
    __syncthreads();

    for (int tile = blockIdx.x; tile < NTILES; tile += EDGE_GRID) {
        int item = tile * 128 + tid;
        int b = item & (BB - 1);
        int e = item >> 4;
        int r = row[e], c = col[e];

        // a = silu(p1[b,r] + p2[b,c])  (b1 folded into p1; d2 == 0 always)
        const float4* q1 = reinterpret_cast<const float4*>(d_p1 + (size_t)(b * NN + r) * HH);
        const float4* q2 = reinterpret_cast<const float4*>(d_p2 + (size_t)(b * NN + c) * HH);
        uint4* arow4 = reinterpret_cast<uint4*>(sAu + tid * PAD_A);
        #pragma unroll
        for (int i4 = 0; i4 < 16; i4++) {
            float4 u = q1[i4];
            float4 v = q2[i4];
            uint4 t;
            t.x = f2tf32(silu(u.x + v.x));
            t.y = f2tf32(silu(u.y + v.y));
            t.z = f2tf32(silu(u.z + v.z));
            t.w = f2tf32(silu(u.w + v.w));
            arow4[i4] = t;
        }
        __syncwarp();

        // GEMM: raw_m = A @ eW2
        float acc[2][8][4];
        #pragma unroll
        for (int mt = 0; mt < 2; mt++)
            #pragma unroll
            for (int j = 0; j < 8; j++)
                #pragma unroll
                for (int q = 0; q < 4; q++) acc[mt][j][q] = 0.0f;

        #pragma unroll
        for (int ks = 0; ks < 8; ks++) {
            uint32_t af[2][4];
            #pragma unroll
            for (int mt = 0; mt < 2; mt++) {
                int rr = base + mt * 16 + g;
                int cc = ks * 8 + tg;
                af[mt][0] = sAu[rr * PAD_A + cc];
                af[mt][1] = sAu[(rr + 8) * PAD_A + cc];
                af[mt][2] = sAu[rr * PAD_A + cc + 4];
                af[mt][3] = sAu[(rr + 8) * PAD_A + cc + 4];
            }
            uint32_t bf[8][2];
            #pragma unroll
            for (int j = 0; j < 8; j++) {
                bf[j][0] = sW2[(ks * 8 + tg) * PAD_B + j * 8 + g];
                bf[j][1] = sW2[(ks * 8 + tg + 4) * PAD_B + j * 8 + g];
            }
            #pragma unroll
            for (int mt = 0; mt < 2; mt++)
                #pragma unroll
                for (int j = 0; j < 8; j++) mma_tf32(acc[mt][j], af[mt], bf[j]);
        }

        // epilogue: m = silu(raw + b2) -> smem rows
        #pragma unroll
        for (int mt = 0; mt < 2; mt++) {
            int r0 = base + mt * 16 + g;
            #pragma unroll
            for (int j = 0; j < 8; j++) {
                int c0 = j * 8 + tg * 2;
                sAf[r0 * PAD_A + c0]           = silu(acc[mt][j][0] + sB2[c0]);
                sAf[r0 * PAD_A + c0 + 1]       = silu(acc[mt][j][1] + sB2[c0 + 1]);
                sAf[(r0 + 8) * PAD_A + c0]     = silu(acc[mt][j][2] + sB2[c0]);
                sAf[(r0 + 8) * PAD_A + c0 + 1] = silu(acc[mt][j][3] + sB2[c0 + 1]);
            }
        }
        __syncwarp();

        // row writeback of m
        {
            const float4* myrow = reinterpret_cast<const float4*>(sAf + tid * PAD_A);
            float4* om = reinterpret_cast<float4*>(d_m + (size_t)item * HH);
            #pragma unroll
            for (int i4 = 0; i4 < 16; i4++) om[i4] = myrow[i4];
        }
        __syncwarp();
    }
}

// ---- gather + node update ----
__global__ void node_kernel(const float* __restrict__ nW1,
                            const float* __restrict__ nb1,
                            const float* __restrict__ nW2,
                            const float* __restrict__ nb2,
                            const float* __restrict__ lng,
                            const float* __restrict__ lnb) {
    int node = blockIdx.x;
    int k = threadIdx.x;
    int b = node >> 10, n = node & (NN - 1);
    __shared__ float x[2 * HH];
    __shared__ float y[HH];
    __shared__ float red[4];

    int s = d_rowptr[n];
    int t = d_rowptr[n + 1];

    float agg = 0.0f;
    for (int j = s; j < t; j++) {
        int e = d_eidx[j];
        agg += d_m[((size_t)e * BB + b) * HH + k];
    }

    float hk = d_h[node * HH + k];
    x[k] = hk;
    x[HH + k] = agg;
    __syncthreads();

    float u1 = nb1[k];
    #pragma unroll 8
    for (int i = 0; i < 2 * HH; i++) u1 += x[i] * nW1[i * HH + k];
    y[k] = silu(u1);
    __syncthreads();

    float u = nb2[k];
    #pragma unroll 8
    for (int i = 0; i < HH; i++) u += y[i] * nW2[i * HH + k];
    float hn = hk + u;

    float v = hn;
    #pragma unroll
    for (int o = 16; o; o >>= 1) v += __shfl_xor_sync(0xffffffffu, v, o);
    if ((k & 31) == 0) red[k >> 5] = v;
    __syncthreads();
    float mu = (red[0] + red[1]) * (1.0f / HH);
    float dv = hn - mu;
    float v2 = dv * dv;
    #pragma unroll
    for (int o = 16; o; o >>= 1) v2 += __shfl_xor_sync(0xffffffffu, v2, o);
    if ((k & 31) == 0) red[2 + (k >> 5)] = v2;
    __syncthreads();
    float var = (red[2] + red[3]) * (1.0f / HH);
    d_h[node * HH + k] = dv * rsqrtf(var + 1e-5f) * lng[k] + lnb[k];
}

__global__ void out_kernel(const float* __restrict__ oW1,
                           const float* __restrict__ ob1,
                           const float* __restrict__ oW2,
                           const float* __restrict__ ob2,
                           float* __restrict__ out) {
    int node = blockIdx.x;
    int k = threadIdx.x;
    __shared__ float x[HH];
    __shared__ float r[HH];
    x[k] = d_h[node * HH + k];
    __syncthreads();
    float acc = ob1[k];
    #pragma unroll 8
    for (int i = 0; i < HH; i++) acc += x[i] * oW1[i * HH + k];
    r[k] = fmaxf(acc, 0.0f);
    __syncthreads();
    if (k < 3) {
        float o = ob2[k];
        #pragma unroll 8
        for (int i = 0; i < HH; i++) o += r[i] * oW2[i * 3 + k];
        out[node * 3 + k] = o;
    }
}

extern "C" void kernel_launch(void* const* d_in, const int* in_sizes, int n_in,
                              void* d_out, int out_size) {
    const float* z   = (const float*)d_in[0];
    const int*   ei  = (const int*)d_in[1];
    const float* nf  = (const float*)d_in[2];
    const float* Wg  = (const float*)d_in[3];
    const float* bg  = (const float*)d_in[4];
    const float* Wn  = (const float*)d_in[5];
    const float* bn  = (const float*)d_in[6];
    const float* eW1 = (const float*)d_in[7];
    const float* eb1 = (const float*)d_in[8];
    const float* eW2 = (const float*)d_in[9];
    const float* eb2 = (const float*)d_in[10];
    const float* nW1 = (const float*)d_in[14];
    const float* nb1 = (const float*)d_in[15];
    const float* nW2 = (const float*)d_in[16];
    const float* nb2 = (const float*)d_in[17];
    const float* lng = (const float*)d_in[18];
    const float* lnb = (const float*)d_in[19];
    const float* oW1 = (const float*)d_in[20];
    const float* ob1 = (const float*)d_in[21];
    const float* oW2 = (const float*)d_in[22];
    const float* ob2 = (const float*)d_in[23];

    cudaFuncSetAttribute((const void*)edge_kernel,
                         cudaFuncAttributeMaxDynamicSharedMemorySize, SME_TOTAL);

    g_kernel<<<1, 1024>>>(z, Wg, bg);
    h_kernel<<<BB * NN, HH>>>(nf, Wn, bn);
    csr_kernel<<<1, 1024>>>(ei);

    for (int l = 0; l < LL; l++) {
        proj1_kernel<<<BB * NN, HH>>>(eW1 + (size_t)l * 129 * HH, eb1 + l * HH);
        proj2_kernel<<<BB * NN, HH>>>(eW1 + (size_t)l * 129 * HH);
        edge_kernel<<<EDGE_GRID, 128, SME_TOTAL>>>(
            ei, ei + EE,
            eW2 + (size_t)l * HH * HH, eb2 + l * HH);
        node_kernel<<<BB * NN, HH>>>(
            nW1 + (size_t)l * 2 * HH * HH, nb1 + l * HH,
            nW2 + (size_t)l * HH * HH, nb2 + l * HH,
            lng + l * HH, lnb + l * HH);
    }

    out_kernel<<<BB * NN, HH>>>(oW1, ob1, oW2, ob2, (float*)d_out);
}

// round 7
// speedup vs baseline: 6.1474x; 1.4250x over previous
#include <cuda_runtime.h>
#include <cstdint>

#define BB 16
#define LATENT 128
#define NN 1024
#define EE 32768
#define HH 64
#define LL 4
#define TPB 256                    // tiles per batch: EE/128
#define NTILES (BB * TPB)          // 4096
#define EDGE_GRID 592              // 148 SMs * 4 CTAs

// ---- scratch (device globals; no allocations allowed) ----
__device__ float d_g[BB * HH];
__device__ float d_h[BB * NN * HH];
__device__ float d_p1[BB * NN * HH];
__device__ float d_p2[BB * NN * HH];
__device__ float d_agg[BB * NN * HH];     // fused aggregation target (4 MB)
__device__ int   d_rowptr[NN + 1];
__device__ int   d_rs[EE];                // row, CSR-sorted
__device__ int   d_cs[EE];                // col, CSR-sorted

__device__ __forceinline__ float silu(float x) {
    return x / (1.0f + __expf(-x));
}

__device__ __forceinline__ uint32_t f2tf32(float x) {
    uint32_t r;
    asm("cvt.rna.tf32.f32 %0, %1;" : "=r"(r) : "f"(x));
    return r;
}

__device__ __forceinline__ void mma_tf32(float* c, const uint32_t* a, const uint32_t* b) {
    asm volatile(
        "mma.sync.aligned.m16n8k8.row.col.f32.tf32.tf32.f32 "
        "{%0,%1,%2,%3}, {%4,%5,%6,%7}, {%8,%9}, {%0,%1,%2,%3};"
        : "+f"(c[0]), "+f"(c[1]), "+f"(c[2]), "+f"(c[3])
        : "r"(a[0]), "r"(a[1]), "r"(a[2]), "r"(a[3]), "r"(b[0]), "r"(b[1]));
}

// SMEM layout (edge kernel)
#define PAD_A 68
#define PAD_B 72
#define SME_A    0                           // 128*68*4 = 34816
#define SME_W2   34816                       // 64*72*4 = 18432
#define SME_BIAS (SME_W2 + 18432)            // b2: 256
#define SME_R    (SME_BIAS + 256)            // r per thread: 512
#define SME_TOTAL (SME_R + 512)

// ---- g = z @ Wg + bg ----
__global__ void g_kernel(const float* __restrict__ z,
                         const float* __restrict__ Wg,
                         const float* __restrict__ bg) {
    int t = blockIdx.x * blockDim.x + threadIdx.x;
    int b = t >> 6, k = t & 63;
    float acc = bg[k];
    const float* zr = z + b * LATENT;
    #pragma unroll 8
    for (int i = 0; i < LATENT; i++) acc += zr[i] * Wg[i * HH + k];
    d_g[t] = acc;
}

// ---- h[b,n,k] = nf[n] @ Wn + bn + g[b] ----
__global__ void h_kernel(const float* __restrict__ nf,
                         const float* __restrict__ Wn,
                         const float* __restrict__ bn) {
    int node = blockIdx.x;
    int k = threadIdx.x;
    int b = node >> 10, n = node & (NN - 1);
    float v = bn[k] + d_g[b * HH + k];
    v += nf[n * 3 + 0] * Wn[0 * HH + k]
       + nf[n * 3 + 1] * Wn[1 * HH + k]
       + nf[n * 3 + 2] * Wn[2 * HH + k];
    d_h[node * HH + k] = v;
}

// ---- CSR build: hist + scan + scatter of (row, col) pairs ----
__global__ void csr_kernel(const int* __restrict__ row,
                           const int* __restrict__ col) {
    __shared__ int sc[NN];
    __shared__ int wo[NN];
    int t = threadIdx.x;
    sc[t] = 0;
    __syncthreads();
    for (int e = t; e < EE; e += 1024) atomicAdd(&sc[row[e]], 1);
    __syncthreads();
    int v = sc[t];
    #pragma unroll
    for (int o = 1; o < NN; o <<= 1) {
        int u = (t >= o) ? sc[t - o] : 0;
        __syncthreads();
        sc[t] += u;
        __syncthreads();
    }
    d_rowptr[t + 1] = sc[t];
    if (t == 0) d_rowptr[0] = 0;
    wo[t] = sc[t] - v;
    __syncthreads();
    for (int e = t; e < EE; e += 1024) {
        int r = row[e];
        int p = atomicAdd(&wo[r], 1);
        d_rs[p] = r;
        d_cs[p] = col[e];
    }
}

// ---- p1 = h @ eW1[0:64] + eb1 ----
__global__ void proj1_kernel(const float* __restrict__ eW1,
                             const float* __restrict__ eb1) {
    int node = blockIdx.x;
    int k = threadIdx.x;
    __shared__ float x[HH];
    x[k] = d_h[node * HH + k];
    __syncthreads();
    float a1 = eb1[k];
    #pragma unroll 8
    for (int i = 0; i < HH; i++) a1 += x[i] * eW1[i * HH + k];
    d_p1[node * HH + k] = a1;
}

// ---- p2 = h @ eW1[64:128] ----
__global__ void proj2_kernel(const float* __restrict__ eW1) {
    int node = blockIdx.x;
    int k = threadIdx.x;
    __shared__ float x[HH];
    x[k] = d_h[node * HH + k];
    __syncthreads();
    float a2 = 0.0f;
    #pragma unroll 8
    for (int i = 0; i < HH; i++) a2 += x[i] * eW1[(HH + i) * HH + k];
    d_p2[node * HH + k] = a2;
}

// ---- fused edge kernel: CSR-ordered tiles, GEMM, segmented reduce -> d_agg ----
__global__ void __launch_bounds__(128) edge_kernel(
    const float* __restrict__ eW2, const float* __restrict__ eb2) {
    extern __shared__ __align__(16) char smem[];
    float*    sAf = (float*)(smem + SME_A);
    uint32_t* sAu = (uint32_t*)(smem + SME_A);
    uint32_t* sW2 = (uint32_t*)(smem + SME_W2);
    float*    sB2 = (float*)(smem + SME_BIAS);
    int*      sR  = (int*)(smem + SME_R);

    int tid = threadIdx.x;
    int wid = tid >> 5;
    int lane = tid & 31;
    int g = lane >> 2;
    int tg = lane & 3;
    int base = wid * 32;

    for (int idx = tid; idx < HH * HH; idx += 128) {
        int i = idx >> 6;
        int n = idx & 63;
        sW2[i * PAD_B + n] = f2tf32(eW2[idx]);
    }
    if (tid < HH) sB2[tid] = eb2[tid];
    __syncthreads();

    for (int tile = blockIdx.x; tile < NTILES; tile += EDGE_GRID) {
        int b = tile >> 8;              // tile / TPB
        int j = (tile & (TPB - 1)) * 128 + tid;   // CSR position
        int r = d_rs[j], c = d_cs[j];
        sR[tid] = r;

        // a = silu(p1[b,r] + p2[b,c])
        const float4* q1 = reinterpret_cast<const float4*>(d_p1 + (size_t)(b * NN + r) * HH);
        const float4* q2 = reinterpret_cast<const float4*>(d_p2 + (size_t)(b * NN + c) * HH);
        uint4* arow4 = reinterpret_cast<uint4*>(sAu + tid * PAD_A);
        #pragma unroll
        for (int i4 = 0; i4 < 16; i4++) {
            float4 u = q1[i4];
            float4 v = q2[i4];
            uint4 t;
            t.x = f2tf32(silu(u.x + v.x));
            t.y = f2tf32(silu(u.y + v.y));
            t.z = f2tf32(silu(u.z + v.z));
            t.w = f2tf32(silu(u.w + v.w));
            arow4[i4] = t;
        }
        __syncwarp();

        // GEMM: raw_m = A @ eW2
        float acc[2][8][4];
        #pragma unroll
        for (int mt = 0; mt < 2; mt++)
            #pragma unroll
            for (int jj = 0; jj < 8; jj++)
                #pragma unroll
                for (int q = 0; q < 4; q++) acc[mt][jj][q] = 0.0f;

        #pragma unroll
        for (int ks = 0; ks < 8; ks++) {
            uint32_t af[2][4];
            #pragma unroll
            for (int mt = 0; mt < 2; mt++) {
                int rr = base + mt * 16 + g;
                int cc = ks * 8 + tg;
                af[mt][0] = sAu[rr * PAD_A + cc];
                af[mt][1] = sAu[(rr + 8) * PAD_A + cc];
                af[mt][2] = sAu[rr * PAD_A + cc + 4];
                af[mt][3] = sAu[(rr + 8) * PAD_A + cc + 4];
            }
            uint32_t bf[8][2];
            #pragma unroll
            for (int jj = 0; jj < 8; jj++) {
                bf[jj][0] = sW2[(ks * 8 + tg) * PAD_B + jj * 8 + g];
                bf[jj][1] = sW2[(ks * 8 + tg + 4) * PAD_B + jj * 8 + g];
            }
            #pragma unroll
            for (int mt = 0; mt < 2; mt++)
                #pragma unroll
                for (int jj = 0; jj < 8; jj++) mma_tf32(acc[mt][jj], af[mt], bf[jj]);
        }

        // epilogue: m = silu(raw + b2) -> smem rows
        #pragma unroll
        for (int mt = 0; mt < 2; mt++) {
            int r0 = base + mt * 16 + g;
            #pragma unroll
            for (int jj = 0; jj < 8; jj++) {
                int c0 = jj * 8 + tg * 2;
                sAf[r0 * PAD_A + c0]           = silu(acc[mt][jj][0] + sB2[c0]);
                sAf[r0 * PAD_A + c0 + 1]       = silu(acc[mt][jj][1] + sB2[c0 + 1]);
                sAf[(r0 + 8) * PAD_A + c0]     = silu(acc[mt][jj][2] + sB2[c0]);
                sAf[(r0 + 8) * PAD_A + c0 + 1] = silu(acc[mt][jj][3] + sB2[c0 + 1]);
            }
        }
        __syncthreads();

        // segmented reduction: thread = (column k2, half hh); rows CSR-contiguous
        {
            int k2 = tid & 63;
            int hh = tid >> 6;
            int r0 = hh * 64;
            int rcur = sR[r0];
            float a = 0.0f;
            #pragma unroll 8
            for (int rr = r0; rr < r0 + 64; rr++) {
                int rn = sR[rr];
                if (rn != rcur) {
                    atomicAdd(&d_agg[((size_t)b * NN + rcur) * HH + k2], a);
                    a = 0.0f;
                    rcur = rn;
                }
                a += sAf[rr * PAD_A + k2];
            }
            atomicAdd(&d_agg[((size_t)b * NN + rcur) * HH + k2], a);
        }
        __syncthreads();
    }
}

// ---- node update: coalesced agg read, MLP, LN; re-zero agg for next layer ----
__global__ void node_kernel(const float* __restrict__ nW1,
                            const float* __restrict__ nb1,
                            const float* __restrict__ nW2,
                            const float* __restrict__ nb2,
                            const float* __restrict__ lng,
                            const float* __restrict__ lnb) {
    int node = blockIdx.x;
    int k = threadIdx.x;
    __shared__ float x[2 * HH];
    __shared__ float y[HH];
    __shared__ float red[4];

    float hk = d_h[node * HH + k];
    float ak = d_agg[node * HH + k];
    d_agg[node * HH + k] = 0.0f;     // restore invariant for next layer / replay
    x[k] = hk;
    x[HH + k] = ak;
    __syncthreads();

    float u1 = nb1[k];
    #pragma unroll 8
    for (int i = 0; i < 2 * HH; i++) u1 += x[i] * nW1[i * HH + k];
    y[k] = silu(u1);
    __syncthreads();

    float u = nb2[k];
    #pragma unroll 8
    for (int i = 0; i < HH; i++) u += y[i] * nW2[i * HH + k];
    float hn = hk + u;

    float v = hn;
    #pragma unroll
    for (int o = 16; o; o >>= 1) v += __shfl_xor_sync(0xffffffffu, v, o);
    if ((k & 31) == 0) red[k >> 5] = v;
    __syncthreads();
    float mu = (red[0] + red[1]) * (1.0f / HH);
    float dv = hn - mu;
    float v2 = dv * dv;
    #pragma unroll
    for (int o = 16; o; o >>= 1) v2 += __shfl_xor_sync(0xffffffffu, v2, o);
    if ((k & 31) == 0) red[2 + (k >> 5)] = v2;
    __syncthreads();
    float var = (red[2] + red[3]) * (1.0f / HH);
    d_h[node * HH + k] = dv * rsqrtf(var + 1e-5f) * lng[k] + lnb[k];
}

__global__ void out_kernel(const float* __restrict__ oW1,
                           const float* __restrict__ ob1,
                           const float* __restrict__ oW2,
                           const float* __restrict__ ob2,
                           float* __restrict__ out) {
    int node = blockIdx.x;
    int k = threadIdx.x;
    __shared__ float x[HH];
    __shared__ float r[HH];
    x[k] = d_h[node * HH + k];
    __syncthreads();
    float acc = ob1[k];
    #pragma unroll 8
    for (int i = 0; i < HH; i++) acc += x[i] * oW1[i * HH + k];
    r[k] = fmaxf(acc, 0.0f);
    __syncthreads();
    if (k < 3) {
        float o = ob2[k];
        #pragma unroll 8
        for (int i = 0; i < HH; i++) o += r[i] * oW2[i * 3 + k];
        out[node * 3 + k] = o;
    }
}

extern "C" void kernel_launch(void* const* d_in, const int* in_sizes, int n_in,
                              void* d_out, int out_size) {
    const float* z   = (const float*)d_in[0];
    const int*   ei  = (const int*)d_in[1];
    const float* nf  = (const float*)d_in[2];
    const float* Wg  = (const float*)d_in[3];
    const float* bg  = (const float*)d_in[4];
    const float* Wn  = (const float*)d_in[5];
    const float* bn  = (const float*)d_in[6];
    const float* eW1 = (const float*)d_in[7];
    const float* eb1 = (const float*)d_in[8];
    const float* eW2 = (const float*)d_in[9];
    const float* eb2 = (const float*)d_in[10];
    const float* nW1 = (const float*)d_in[14];
    const float* nb1 = (const float*)d_in[15];
    const float* nW2 = (const float*)d_in[16];
    const float* nb2 = (const float*)d_in[17];
    const float* lng = (const float*)d_in[18];
    const float* lnb = (const float*)d_in[19];
    const float* oW1 = (const float*)d_in[20];
    const float* ob1 = (const float*)d_in[21];
    const float* oW2 = (const float*)d_in[22];
    const float* ob2 = (const float*)d_in[23];

    // defensive: ensure agg invariant even if a prior run aborted mid-graph
    void* pAgg;
    cudaGetSymbolAddress(&pAgg, d_agg);
    cudaMemsetAsync(pAgg, 0, sizeof(float) * BB * NN * HH);

    cudaFuncSetAttribute((const void*)edge_kernel,
                         cudaFuncAttributeMaxDynamicSharedMemorySize, SME_TOTAL);

    g_kernel<<<1, 1024>>>(z, Wg, bg);
    h_kernel<<<BB * NN, HH>>>(nf, Wn, bn);
    csr_kernel<<<1, 1024>>>(ei, ei + EE);

    for (int l = 0; l < LL; l++) {
        proj1_kernel<<<BB * NN, HH>>>(eW1 + (size_t)l * 129 * HH, eb1 + l * HH);
        proj2_kernel<<<BB * NN, HH>>>(eW1 + (size_t)l * 129 * HH);
        edge_kernel<<<EDGE_GRID, 128, SME_TOTAL>>>(
            eW2 + (size_t)l * HH * HH, eb2 + l * HH);
        node_kernel<<<BB * NN, HH>>>(
            nW1 + (size_t)l * 2 * HH * HH, nb1 + l * HH,
            nW2 + (size_t)l * HH * HH, nb2 + l * HH,
            lng + l * HH, lnb + l * HH);
    }

    out_kernel<<<BB * NN, HH>>>(oW1, ob1, oW2, ob2, (float*)d_out);
}

// round 8
// speedup vs baseline: 6.3812x; 1.0380x over previous
#include <cuda_runtime.h>
#include <cstdint>

#define BB 16
#define LATENT 128
#define NN 1024
#define EE 32768
#define HH 64
#define LL 4
#define TPB 256                    // tiles per batch: EE/128
#define NTILES (BB * TPB)          // 4096
#define EDGE_GRID 592              // 148 SMs * 4 CTAs

// ---- scratch (device globals; no allocations allowed) ----
__device__ float d_g[BB * HH];
__device__ float d_h[BB * NN * HH];
__device__ float d_p1[BB * NN * HH];
__device__ float d_p2[BB * NN * HH];
__device__ float d_agg[BB * NN * HH];
__device__ int   d_rowptr[NN + 1];
__device__ int   d_rs[EE];                // row, CSR-sorted
__device__ int   d_cs[EE];                // col, CSR-sorted

__device__ __forceinline__ float silu(float x) {
    return x / (1.0f + __expf(-x));
}

__device__ __forceinline__ uint32_t f2tf32(float x) {
    uint32_t r;
    asm("cvt.rna.tf32.f32 %0, %1;" : "=r"(r) : "f"(x));
    return r;
}

__device__ __forceinline__ void mma_tf32(float* c, const uint32_t* a, const uint32_t* b) {
    asm volatile(
        "mma.sync.aligned.m16n8k8.row.col.f32.tf32.tf32.f32 "
        "{%0,%1,%2,%3}, {%4,%5,%6,%7}, {%8,%9}, {%0,%1,%2,%3};"
        : "+f"(c[0]), "+f"(c[1]), "+f"(c[2]), "+f"(c[3])
        : "r"(a[0]), "r"(a[1]), "r"(a[2]), "r"(a[3]), "r"(b[0]), "r"(b[1]));
}

// SMEM layout (edge kernel)
#define PAD_A 68
#define PAD_B 72
#define SME_A    0
#define SME_W2   34816
#define SME_BIAS (SME_W2 + 18432)
#define SME_R    (SME_BIAS + 256)
#define SME_TOTAL (SME_R + 512)

// ---- g = z @ Wg + bg ----
__global__ void g_kernel(const float* __restrict__ z,
                         const float* __restrict__ Wg,
                         const float* __restrict__ bg) {
    int t = blockIdx.x * blockDim.x + threadIdx.x;
    int b = t >> 6, k = t & 63;
    float acc = bg[k];
    const float* zr = z + b * LATENT;
    #pragma unroll 8
    for (int i = 0; i < LATENT; i++) acc += zr[i] * Wg[i * HH + k];
    d_g[t] = acc;
}

// ---- h + proj for layer 0 ----
__global__ void h_kernel(const float* __restrict__ nf,
                         const float* __restrict__ Wn,
                         const float* __restrict__ bn,
                         const float* __restrict__ eW1,
                         const float* __restrict__ eb1) {
    int node = blockIdx.x;
    int k = threadIdx.x;
    int b = node >> 10, n = node & (NN - 1);
    __shared__ float x[HH];
    float v = bn[k] + d_g[b * HH + k];
    v += nf[n * 3 + 0] * Wn[0 * HH + k]
       + nf[n * 3 + 1] * Wn[1 * HH + k]
       + nf[n * 3 + 2] * Wn[2 * HH + k];
    d_h[node * HH + k] = v;
    x[k] = v;
    __syncthreads();
    float a1 = eb1[k], a2 = 0.0f;
    #pragma unroll 8
    for (int i = 0; i < HH; i++) {
        float xv = x[i];
        a1 += xv * eW1[i * HH + k];
        a2 += xv * eW1[(HH + i) * HH + k];
    }
    d_p1[node * HH + k] = a1;
    d_p2[node * HH + k] = a2;
}

// ---- CSR build: hist + scan + scatter of (row, col) pairs ----
__global__ void csr_kernel(const int* __restrict__ row,
                           const int* __restrict__ col) {
    __shared__ int sc[NN];
    __shared__ int wo[NN];
    int t = threadIdx.x;
    sc[t] = 0;
    __syncthreads();
    for (int e = t; e < EE; e += 1024) atomicAdd(&sc[row[e]], 1);
    __syncthreads();
    int v = sc[t];
    #pragma unroll
    for (int o = 1; o < NN; o <<= 1) {
        int u = (t >= o) ? sc[t - o] : 0;
        __syncthreads();
        sc[t] += u;
        __syncthreads();
    }
    d_rowptr[t + 1] = sc[t];
    if (t == 0) d_rowptr[0] = 0;
    wo[t] = sc[t] - v;
    __syncthreads();
    for (int e = t; e < EE; e += 1024) {
        int r = row[e];
        int p = atomicAdd(&wo[r], 1);
        d_rs[p] = r;
        d_cs[p] = col[e];
    }
}

// ---- fused edge kernel: CSR-ordered tiles, GEMM, segmented reduce -> d_agg ----
__global__ void __launch_bounds__(128) edge_kernel(
    const float* __restrict__ eW2, const float* __restrict__ eb2) {
    extern __shared__ __align__(16) char smem[];
    float*    sAf = (float*)(smem + SME_A);
    uint32_t* sAu = (uint32_t*)(smem + SME_A);
    uint32_t* sW2 = (uint32_t*)(smem + SME_W2);
    float*    sB2 = (float*)(smem + SME_BIAS);
    int*      sR  = (int*)(smem + SME_R);

    int tid = threadIdx.x;
    int wid = tid >> 5;
    int lane = tid & 31;
    int g = lane >> 2;
    int tg = lane & 3;
    int base = wid * 32;

    for (int idx = tid; idx < HH * HH; idx += 128) {
        int i = idx >> 6;
        int n = idx & 63;
        sW2[i * PAD_B + n] = f2tf32(eW2[idx]);
    }
    if (tid < HH) sB2[tid] = eb2[tid];
    __syncthreads();

    for (int tile = blockIdx.x; tile < NTILES; tile += EDGE_GRID) {
        int b = tile >> 8;
        int j = (tile & (TPB - 1)) * 128 + tid;
        int r = d_rs[j], c = d_cs[j];
        sR[tid] = r;

        const float4* q1 = reinterpret_cast<const float4*>(d_p1 + (size_t)(b * NN + r) * HH);
        const float4* q2 = reinterpret_cast<const float4*>(d_p2 + (size_t)(b * NN + c) * HH);
        uint4* arow4 = reinterpret_cast<uint4*>(sAu + tid * PAD_A);
        #pragma unroll
        for (int i4 = 0; i4 < 16; i4++) {
            float4 u = q1[i4];
            float4 v = q2[i4];
            uint4 t;
            t.x = f2tf32(silu(u.x + v.x));
            t.y = f2tf32(silu(u.y + v.y));
            t.z = f2tf32(silu(u.z + v.z));
            t.w = f2tf32(silu(u.w + v.w));
            arow4[i4] = t;
        }
        __syncwarp();

        // GEMM: raw_m = A @ eW2
        float acc[2][8][4];
        #pragma unroll
        for (int mt = 0; mt < 2; mt++)
            #pragma unroll
            for (int jj = 0; jj < 8; jj++)
                #pragma unroll
                for (int q = 0; q < 4; q++) acc[mt][jj][q] = 0.0f;

        #pragma unroll
        for (int ks = 0; ks < 8; ks++) {
            uint32_t af[2][4];
            #pragma unroll
            for (int mt = 0; mt < 2; mt++) {
                int rr = base + mt * 16 + g;
                int cc = ks * 8 + tg;
                af[mt][0] = sAu[rr * PAD_A + cc];
                af[mt][1] = sAu[(rr + 8) * PAD_A + cc];
                af[mt][2] = sAu[rr * PAD_A + cc + 4];
                af[mt][3] = sAu[(rr + 8) * PAD_A + cc + 4];
            }
            uint32_t bf[8][2];
            #pragma unroll
            for (int jj = 0; jj < 8; jj++) {
                bf[jj][0] = sW2[(ks * 8 + tg) * PAD_B + jj * 8 + g];
                bf[jj][1] = sW2[(ks * 8 + tg + 4) * PAD_B + jj * 8 + g];
            }
            #pragma unroll
            for (int mt = 0; mt < 2; mt++)
                #pragma unroll
                for (int jj = 0; jj < 8; jj++) mma_tf32(acc[mt][jj], af[mt], bf[jj]);
        }

        // epilogue: m = silu(raw + b2) -> smem rows
        #pragma unroll
        for (int mt = 0; mt < 2; mt++) {
            int r0 = base + mt * 16 + g;
            #pragma unroll
            for (int jj = 0; jj < 8; jj++) {
                int c0 = jj * 8 + tg * 2;
                sAf[r0 * PAD_A + c0]           = silu(acc[mt][jj][0] + sB2[c0]);
                sAf[r0 * PAD_A + c0 + 1]       = silu(acc[mt][jj][1] + sB2[c0 + 1]);
                sAf[(r0 + 8) * PAD_A + c0]     = silu(acc[mt][jj][2] + sB2[c0]);
                sAf[(r0 + 8) * PAD_A + c0 + 1] = silu(acc[mt][jj][3] + sB2[c0 + 1]);
            }
        }
        __syncthreads();

        // segmented reduction: thread = (column k2, half hh)
        {
            int k2 = tid & 63;
            int hh = tid >> 6;
            int r0 = hh * 64;
            int rcur = sR[r0];
            float a = 0.0f;
            #pragma unroll 8
            for (int rr = r0; rr < r0 + 64; rr++) {
                int rn = sR[rr];
                if (rn != rcur) {
                    atomicAdd(&d_agg[((size_t)b * NN + rcur) * HH + k2], a);
                    a = 0.0f;
                    rcur = rn;
                }
                a += sAf[rr * PAD_A + k2];
            }
            atomicAdd(&d_agg[((size_t)b * NN + rcur) * HH + k2], a);
        }
        __syncthreads();
    }
}

// ---- node update + fused proj for next layer ----
__global__ void node_kernel(const float* __restrict__ nW1,
                            const float* __restrict__ nb1,
                            const float* __restrict__ nW2,
                            const float* __restrict__ nb2,
                            const float* __restrict__ lng,
                            const float* __restrict__ lnb,
                            const float* __restrict__ eW1n,   // next layer eW1 (or null)
                            const float* __restrict__ eb1n) { // next layer eb1 (or null)
    int node = blockIdx.x;
    int k = threadIdx.x;
    __shared__ float x[2 * HH];
    __shared__ float y[HH];
    __shared__ float red[4];

    float hk = d_h[node * HH + k];
    float ak = d_agg[node * HH + k];
    d_agg[node * HH + k] = 0.0f;
    x[k] = hk;
    x[HH + k] = ak;
    __syncthreads();

    float u1 = nb1[k];
    #pragma unroll 8
    for (int i = 0; i < 2 * HH; i++) u1 += x[i] * nW1[i * HH + k];
    y[k] = silu(u1);
    __syncthreads();

    float u = nb2[k];
    #pragma unroll 8
    for (int i = 0; i < HH; i++) u += y[i] * nW2[i * HH + k];
    float hn = hk + u;

    float v = hn;
    #pragma unroll
    for (int o = 16; o; o >>= 1) v += __shfl_xor_sync(0xffffffffu, v, o);
    if ((k & 31) == 0) red[k >> 5] = v;
    __syncthreads();
    float mu = (red[0] + red[1]) * (1.0f / HH);
    float dv = hn - mu;
    float v2 = dv * dv;
    #pragma unroll
    for (int o = 16; o; o >>= 1) v2 += __shfl_xor_sync(0xffffffffu, v2, o);
    if ((k & 31) == 0) red[2 + (k >> 5)] = v2;
    __syncthreads();
    float var = (red[2] + red[3]) * (1.0f / HH);
    float hnew = dv * rsqrtf(var + 1e-5f) * lng[k] + lnb[k];
    d_h[node * HH + k] = hnew;

    if (eW1n != nullptr) {
        x[k] = hnew;      // reuse smem
        __syncthreads();
        float a1 = eb1n[k], a2 = 0.0f;
        #pragma unroll 8
        for (int i = 0; i < HH; i++) {
            float xv = x[i];
            a1 += xv * eW1n[i * HH + k];
            a2 += xv * eW1n[(HH + i) * HH + k];
        }
        d_p1[node * HH + k] = a1;
        d_p2[node * HH + k] = a2;
    }
}

__global__ void out_kernel(const float* __restrict__ oW1,
                           const float* __restrict__ ob1,
                           const float* __restrict__ oW2,
                           const float* __restrict__ ob2,
                           float* __restrict__ out) {
    int node = blockIdx.x;
    int k = threadIdx.x;
    __shared__ float x[HH];
    __shared__ float r[HH];
    x[k] = d_h[node * HH + k];
    __syncthreads();
    float acc = ob1[k];
    #pragma unroll 8
    for (int i = 0; i < HH; i++) acc += x[i] * oW1[i * HH + k];
    r[k] = fmaxf(acc, 0.0f);
    __syncthreads();
    if (k < 3) {
        float o = ob2[k];
        #pragma unroll 8
        for (int i = 0; i < HH; i++) o += r[i] * oW2[i * 3 + k];
        out[node * 3 + k] = o;
    }
}

extern "C" void kernel_launch(void* const* d_in, const int* in_sizes, int n_in,
                              void* d_out, int out_size) {
    const float* z   = (const float*)d_in[0];
    const int*   ei  = (const int*)d_in[1];
    const float* nf  = (const float*)d_in[2];
    const float* Wg  = (const float*)d_in[3];
    const float* bg  = (const float*)d_in[4];
    const float* Wn  = (const float*)d_in[5];
    const float* bn  = (const float*)d_in[6];
    const float* eW1 = (const float*)d_in[7];
    const float* eb1 = (const float*)d_in[8];
    const float* eW2 = (const float*)d_in[9];
    const float* eb2 = (const float*)d_in[10];
    const float* nW1 = (const float*)d_in[14];
    const float* nb1 = (const float*)d_in[15];
    const float* nW2 = (const float*)d_in[16];
    const float* nb2 = (const float*)d_in[17];
    const float* lng = (const float*)d_in[18];
    const float* lnb = (const float*)d_in[19];
    const float* oW1 = (const float*)d_in[20];
    const float* ob1 = (const float*)d_in[21];
    const float* oW2 = (const float*)d_in[22];
    const float* ob2 = (const float*)d_in[23];

    void* pAgg;
    cudaGetSymbolAddress(&pAgg, d_agg);
    cudaMemsetAsync(pAgg, 0, sizeof(float) * BB * NN * HH);

    cudaFuncSetAttribute((const void*)edge_kernel,
                         cudaFuncAttributeMaxDynamicSharedMemorySize, SME_TOTAL);

    g_kernel<<<1, 1024>>>(z, Wg, bg);
    h_kernel<<<BB * NN, HH>>>(nf, Wn, bn, eW1, eb1);   // h + proj layer 0
    csr_kernel<<<1, 1024>>>(ei, ei + EE);

    for (int l = 0; l < LL; l++) {
        edge_kernel<<<EDGE_GRID, 128, SME_TOTAL>>>(
            eW2 + (size_t)l * HH * HH, eb2 + l * HH);
        const float* eW1n = (l + 1 < LL) ? eW1 + (size_t)(l + 1) * 129 * HH : nullptr;
        const float* eb1n = (l + 1 < LL) ? eb1 + (l + 1) * HH : nullptr;
        node_kernel<<<BB * NN, HH>>>(
            nW1 + (size_t)l * 2 * HH * HH, nb1 + l * HH,
            nW2 + (size_t)l * HH * HH, nb2 + l * HH,
            lng + l * HH, lnb + l * HH,
            eW1n, eb1n);
    }

    out_kernel<<<BB * NN, HH>>>(oW1, ob1, oW2, ob2, (float*)d_out);
}

// round 9
// speedup vs baseline: 7.0789x; 1.1093x over previous
#include <cuda_runtime.h>
#include <cstdint>

#define BB 16
#define LATENT 128
#define NN 1024
#define EE 32768
#define HH 64
#define LL 4
#define TPB 256                    // tiles per batch: EE/128
#define NTILES (BB * TPB)          // 4096
#define EDGE_GRID 444              // 148 SMs * 3 CTAs

// ---- scratch (device globals; no allocations allowed) ----
__device__ float d_g[BB * HH];
__device__ float d_h[BB * NN * HH];
__device__ float d_p1[BB * NN * HH];
__device__ float d_p2[BB * NN * HH];
__device__ float d_agg[BB * NN * HH];
__device__ int   d_rowptr[NN + 1];
__device__ int   d_rs[EE];                // row, CSR-sorted
__device__ int   d_cs[EE];                // col, CSR-sorted

__device__ __forceinline__ float silu(float x) {
    return x / (1.0f + __expf(-x));
}

__device__ __forceinline__ uint32_t f2tf32(float x) {
    uint32_t r;
    asm("cvt.rna.tf32.f32 %0, %1;" : "=r"(r) : "f"(x));
    return r;
}

__device__ __forceinline__ void mma_tf32(float* c, const uint32_t* a, const uint32_t* b) {
    asm volatile(
        "mma.sync.aligned.m16n8k8.row.col.f32.tf32.tf32.f32 "
        "{%0,%1,%2,%3}, {%4,%5,%6,%7}, {%8,%9}, {%0,%1,%2,%3};"
        : "+f"(c[0]), "+f"(c[1]), "+f"(c[2]), "+f"(c[3])
        : "r"(a[0]), "r"(a[1]), "r"(a[2]), "r"(a[3]), "r"(b[0]), "r"(b[1]));
}

// SMEM layout (edge kernel)
#define PAD_A 68
#define PAD_B 72
#define SME_A    0
#define SME_W2   34816
#define SME_BIAS (SME_W2 + 18432)
#define SME_R    (SME_BIAS + 256)
#define SME_TOTAL (SME_R + 512)

// ---- g = z @ Wg + bg ----
__global__ void g_kernel(const float* __restrict__ z,
                         const float* __restrict__ Wg,
                         const float* __restrict__ bg) {
    int t = blockIdx.x * blockDim.x + threadIdx.x;
    int b = t >> 6, k = t & 63;
    float acc = bg[k];
    const float* zr = z + b * LATENT;
    #pragma unroll 8
    for (int i = 0; i < LATENT; i++) acc += zr[i] * Wg[i * HH + k];
    d_g[t] = acc;
}

// ---- h + proj for layer 0 ----
__global__ void h_kernel(const float* __restrict__ nf,
                         const float* __restrict__ Wn,
                         const float* __restrict__ bn,
                         const float* __restrict__ eW1,
                         const float* __restrict__ eb1) {
    int node = blockIdx.x;
    int k = threadIdx.x;
    int b = node >> 10, n = node & (NN - 1);
    __shared__ float x[HH];
    float v = bn[k] + d_g[b * HH + k];
    v += nf[n * 3 + 0] * Wn[0 * HH + k]
       + nf[n * 3 + 1] * Wn[1 * HH + k]
       + nf[n * 3 + 2] * Wn[2 * HH + k];
    d_h[node * HH + k] = v;
    x[k] = v;
    __syncthreads();
    float a1 = eb1[k], a2 = 0.0f;
    #pragma unroll 8
    for (int i = 0; i < HH; i++) {
        float xv = x[i];
        a1 += xv * eW1[i * HH + k];
        a2 += xv * eW1[(HH + i) * HH + k];
    }
    d_p1[node * HH + k] = a1;
    d_p2[node * HH + k] = a2;
}

// ---- CSR build ----
__global__ void csr_kernel(const int* __restrict__ row,
                           const int* __restrict__ col) {
    __shared__ int sc[NN];
    __shared__ int wo[NN];
    int t = threadIdx.x;
    sc[t] = 0;
    __syncthreads();
    for (int e = t; e < EE; e += 1024) atomicAdd(&sc[row[e]], 1);
    __syncthreads();
    int v = sc[t];
    #pragma unroll
    for (int o = 1; o < NN; o <<= 1) {
        int u = (t >= o) ? sc[t - o] : 0;
        __syncthreads();
        sc[t] += u;
        __syncthreads();
    }
    d_rowptr[t + 1] = sc[t];
    if (t == 0) d_rowptr[0] = 0;
    wo[t] = sc[t] - v;
    __syncthreads();
    for (int e = t; e < EE; e += 1024) {
        int r = row[e];
        int p = atomicAdd(&wo[r], 1);
        d_rs[p] = r;
        d_cs[p] = col[e];
    }
}

// ---- fused edge kernel: 256 thr, split-N warps, GEMM + segmented reduce ----
__global__ void __launch_bounds__(256, 3) edge_kernel(
    const float* __restrict__ eW2, const float* __restrict__ eb2) {
    extern __shared__ __align__(16) char smem[];
    float*    sAf = (float*)(smem + SME_A);
    uint32_t* sAu = (uint32_t*)(smem + SME_A);
    uint32_t* sW2 = (uint32_t*)(smem + SME_W2);
    float*    sB2 = (float*)(smem + SME_BIAS);
    int*      sR  = (int*)(smem + SME_R);

    int tid = threadIdx.x;
    int wid = tid >> 5;
    int lane = tid & 31;
    int g = lane >> 2;
    int tg = lane & 3;
    int rb = wid & 3;          // row block (32 rows)
    int ch = wid >> 2;         // col half (32 cols)

    for (int idx = tid; idx < HH * HH; idx += 256) {
        int i = idx >> 6;
        int n = idx & 63;
        sW2[i * PAD_B + n] = f2tf32(eW2[idx]);
    }
    if (tid < HH) sB2[tid] = eb2[tid];
    __syncthreads();

    int rrow = tid & 127;      // item row this thread gathers
    int half = tid >> 7;       // which 32-col half of the row

    for (int tile = blockIdx.x; tile < NTILES; tile += EDGE_GRID) {
        int b = tile >> 8;
        int jbase = (tile & (TPB - 1)) * 128;

        // gather: each thread loads a half-row of p1 and p2
        {
            int j = jbase + rrow;
            int r = d_rs[j], c = d_cs[j];
            if (half == 0) sR[rrow] = r;
            const float4* q1 = reinterpret_cast<const float4*>(
                d_p1 + (size_t)(b * NN + r) * HH + half * 32);
            const float4* q2 = reinterpret_cast<const float4*>(
                d_p2 + (size_t)(b * NN + c) * HH + half * 32);
            uint4* dst = reinterpret_cast<uint4*>(sAu + rrow * PAD_A + half * 32);
            #pragma unroll
            for (int i4 = 0; i4 < 8; i4++) {
                float4 u = q1[i4];
                float4 v = q2[i4];
                uint4 t;
                t.x = f2tf32(silu(u.x + v.x));
                t.y = f2tf32(silu(u.y + v.y));
                t.z = f2tf32(silu(u.z + v.z));
                t.w = f2tf32(silu(u.w + v.w));
                dst[i4] = t;
            }
        }
        __syncthreads();

        // GEMM: warp computes rows rb*32..+31, cols ch*32..+31
        float acc[2][4][4];
        #pragma unroll
        for (int mt = 0; mt < 2; mt++)
            #pragma unroll
            for (int jj = 0; jj < 4; jj++)
                #pragma unroll
                for (int q = 0; q < 4; q++) acc[mt][jj][q] = 0.0f;

        #pragma unroll
        for (int ks = 0; ks < 8; ks++) {
            uint32_t af[2][4];
            #pragma unroll
            for (int mt = 0; mt < 2; mt++) {
                int rr = rb * 32 + mt * 16 + g;
                int cc = ks * 8 + tg;
                af[mt][0] = sAu[rr * PAD_A + cc];
                af[mt][1] = sAu[(rr + 8) * PAD_A + cc];
                af[mt][2] = sAu[rr * PAD_A + cc + 4];
                af[mt][3] = sAu[(rr + 8) * PAD_A + cc + 4];
            }
            uint32_t bf[4][2];
            #pragma unroll
            for (int jj = 0; jj < 4; jj++) {
                int n = ch * 32 + jj * 8 + g;
                bf[jj][0] = sW2[(ks * 8 + tg) * PAD_B + n];
                bf[jj][1] = sW2[(ks * 8 + tg + 4) * PAD_B + n];
            }
            #pragma unroll
            for (int mt = 0; mt < 2; mt++)
                #pragma unroll
                for (int jj = 0; jj < 4; jj++) mma_tf32(acc[mt][jj], af[mt], bf[jj]);
        }
        __syncthreads();   // A staging reads done before epilogue overwrites

        // epilogue: m = silu(raw + b2) -> smem rows (own col half)
        #pragma unroll
        for (int mt = 0; mt < 2; mt++) {
            int r0 = rb * 32 + mt * 16 + g;
            #pragma unroll
            for (int jj = 0; jj < 4; jj++) {
                int c0 = ch * 32 + jj * 8 + tg * 2;
                sAf[r0 * PAD_A + c0]           = silu(acc[mt][jj][0] + sB2[c0]);
                sAf[r0 * PAD_A + c0 + 1]       = silu(acc[mt][jj][1] + sB2[c0 + 1]);
                sAf[(r0 + 8) * PAD_A + c0]     = silu(acc[mt][jj][2] + sB2[c0]);
                sAf[(r0 + 8) * PAD_A + c0 + 1] = silu(acc[mt][jj][3] + sB2[c0 + 1]);
            }
        }
        __syncthreads();

        // segmented reduction: thread = (column k2, quarter seg); 32 rows each
        {
            int k2 = tid & 63;
            int seg = tid >> 6;
            int r0 = seg * 32;
            int rcur = sR[r0];
            float a = 0.0f;
            #pragma unroll 8
            for (int rr = r0; rr < r0 + 32; rr++) {
                int rn = sR[rr];
                if (rn != rcur) {
                    atomicAdd(&d_agg[((size_t)b * NN + rcur) * HH + k2], a);
                    a = 0.0f;
                    rcur = rn;
                }
                a += sAf[rr * PAD_A + k2];
            }
            atomicAdd(&d_agg[((size_t)b * NN + rcur) * HH + k2], a);
        }
        __syncthreads();
    }
}

// ---- node update + fused proj for next layer ----
__global__ void node_kernel(const float* __restrict__ nW1,
                            const float* __restrict__ nb1,
                            const float* __restrict__ nW2,
                            const float* __restrict__ nb2,
                            const float* __restrict__ lng,
                            const float* __restrict__ lnb,
                            const float* __restrict__ eW1n,
                            const float* __restrict__ eb1n) {
    int node = blockIdx.x;
    int k = threadIdx.x;
    __shared__ float x[2 * HH];
    __shared__ float y[HH];
    __shared__ float red[4];

    float hk = d_h[node * HH + k];
    float ak = d_agg[node * HH + k];
    d_agg[node * HH + k] = 0.0f;
    x[k] = hk;
    x[HH + k] = ak;
    __syncthreads();

    float u1 = nb1[k];
    #pragma unroll 8
    for (int i = 0; i < 2 * HH; i++) u1 += x[i] * nW1[i * HH + k];
    y[k] = silu(u1);
    __syncthreads();

    float u = nb2[k];
    #pragma unroll 8
    for (int i = 0; i < HH; i++) u += y[i] * nW2[i * HH + k];
    float hn = hk + u;

    float v = hn;
    #pragma unroll
    for (int o = 16; o; o >>= 1) v += __shfl_xor_sync(0xffffffffu, v, o);
    if ((k & 31) == 0) red[k >> 5] = v;
    __syncthreads();
    float mu = (red[0] + red[1]) * (1.0f / HH);
    float dv = hn - mu;
    float v2 = dv * dv;
    #pragma unroll
    for (int o = 16; o; o >>= 1) v2 += __shfl_xor_sync(0xffffffffu, v2, o);
    if ((k & 31) == 0) red[2 + (k >> 5)] = v2;
    __syncthreads();
    float var = (red[2] + red[3]) * (1.0f / HH);
    float hnew = dv * rsqrtf(var + 1e-5f) * lng[k] + lnb[k];
    d_h[node * HH + k] = hnew;

    if (eW1n != nullptr) {
        x[k] = hnew;
        __syncthreads();
        float a1 = eb1n[k], a2 = 0.0f;
        #pragma unroll 8
        for (int i = 0; i < HH; i++) {
            float xv = x[i];
            a1 += xv * eW1n[i * HH + k];
            a2 += xv * eW1n[(HH + i) * HH + k];
        }
        d_p1[node * HH + k] = a1;
        d_p2[node * HH + k] = a2;
    }
}

__global__ void out_kernel(const float* __restrict__ oW1,
                           const float* __restrict__ ob1,
                           const float* __restrict__ oW2,
                           const float* __restrict__ ob2,
                           float* __restrict__ out) {
    int node = blockIdx.x;
    int k = threadIdx.x;
    __shared__ float x[HH];
    __shared__ float r[HH];
    x[k] = d_h[node * HH + k];
    __syncthreads();
    float acc = ob1[k];
    #pragma unroll 8
    for (int i = 0; i < HH; i++) acc += x[i] * oW1[i * HH + k];
    r[k] = fmaxf(acc, 0.0f);
    __syncthreads();
    if (k < 3) {
        float o = ob2[k];
        #pragma unroll 8
        for (int i = 0; i < HH; i++) o += r[i] * oW2[i * 3 + k];
        out[node * 3 + k] = o;
    }
}

extern "C" void kernel_launch(void* const* d_in, const int* in_sizes, int n_in,
                              void* d_out, int out_size) {
    const float* z   = (const float*)d_in[0];
    const int*   ei  = (const int*)d_in[1];
    const float* nf  = (const float*)d_in[2];
    const float* Wg  = (const float*)d_in[3];
    const float* bg  = (const float*)d_in[4];
    const float* Wn  = (const float*)d_in[5];
    const float* bn  = (const float*)d_in[6];
    const float* eW1 = (const float*)d_in[7];
    const float* eb1 = (const float*)d_in[8];
    const float* eW2 = (const float*)d_in[9];
    const float* eb2 = (const float*)d_in[10];
    const float* nW1 = (const float*)d_in[14];
    const float* nb1 = (const float*)d_in[15];
    const float* nW2 = (const float*)d_in[16];
    const float* nb2 = (const float*)d_in[17];
    const float* lng = (const float*)d_in[18];
    const float* lnb = (const float*)d_in[19];
    const float* oW1 = (const float*)d_in[20];
    const float* ob1 = (const float*)d_in[21];
    const float* oW2 = (const float*)d_in[22];
    const float* ob2 = (const float*)d_in[23];

    void* pAgg;
    cudaGetSymbolAddress(&pAgg, d_agg);
    cudaMemsetAsync(pAgg, 0, sizeof(float) * BB * NN * HH);

    cudaFuncSetAttribute((const void*)edge_kernel,
                         cudaFuncAttributeMaxDynamicSharedMemorySize, SME_TOTAL);

    g_kernel<<<1, 1024>>>(z, Wg, bg);
    h_kernel<<<BB * NN, HH>>>(nf, Wn, bn, eW1, eb1);
    csr_kernel<<<1, 1024>>>(ei, ei + EE);

    for (int l = 0; l < LL; l++) {
        edge_kernel<<<EDGE_GRID, 256, SME_TOTAL>>>(
            eW2 + (size_t)l * HH * HH, eb2 + l * HH);
        const float* eW1n = (l + 1 < LL) ? eW1 + (size_t)(l + 1) * 129 * HH : nullptr;
        const float* eb1n = (l + 1 < LL) ? eb1 + (l + 1) * HH : nullptr;
        node_kernel<<<BB * NN, HH>>>(
            nW1 + (size_t)l * 2 * HH * HH, nb1 + l * HH,
            nW2 + (size_t)l * HH * HH, nb2 + l * HH,
            lng + l * HH, lnb + l * HH,
            eW1n, eb1n);
    }

    out_kernel<<<BB * NN, HH>>>(oW1, ob1, oW2, ob2, (float*)d_out);
}